// round 5
// baseline (speedup 1.0000x reference)
#include <cuda_runtime.h>

#define EPC 8
#define SMF 8448   // floats of shared: stage buffer (33*256) dominates persistent (7744)

// persistent smem layout (float offsets)
#define S_ABC 0      // 48
#define S_BC  64     // 16x16
#define S_WA  320    // 8x32 float4 (1024 floats)
#define S_Y0  1344   // [t1][tap][c] 8*8*32
#define S_P1  3392   // [t1][w][f]
#define S_P2  5440   // [q2][w][f]
#define S_P3  7488   // [w][f]

__device__ __forceinline__ unsigned long long ffma2(unsigned long long a,
                                                    unsigned long long b,
                                                    unsigned long long c) {
    unsigned long long d;
    asm("fma.rn.f32x2 %0, %1, %2, %3;" : "=l"(d) : "l"(a), "l"(b), "l"(c));
    return d;
}
__device__ __forceinline__ unsigned long long packf2(float lo, float hi) {
    unsigned long long r;
    asm("mov.b64 %0, {%1, %2};" : "=l"(r) : "f"(lo), "f"(hi));
    return r;
}
__device__ __forceinline__ float2 unpackf2(unsigned long long v) {
    float lo, hi;
    asm("mov.b64 {%0, %1}, %2;" : "=f"(lo), "=f"(hi) : "l"(v));
    return make_float2(lo, hi);
}

// scatter Wsrc ([f=32][c=32][t=8]) into transposed padded smem: sm[(t*32+c)*33+f]
#define STAGE_STORE(Wsrc) do {                                              \
    _Pragma("unroll")                                                       \
    for (int r = 0; r < 8; ++r) {                                           \
        int i4 = tid + 256 * r;                                             \
        float4 v = ((const float4*)(Wsrc))[i4];                             \
        int f = i4 >> 6, rem = i4 & 63, c = rem >> 1, tb = (rem & 1) * 4;   \
        sm[((tb + 0) * 32 + c) * 33 + f] = v.x;                             \
        sm[((tb + 1) * 32 + c) * 33 + f] = v.y;                             \
        sm[((tb + 2) * 32 + c) * 33 + f] = v.z;                             \
        sm[((tb + 3) * 32 + c) * 33 + f] = v.w;                             \
    }                                                                       \
} while (0)

__global__ __launch_bounds__(256, 2)
void ntc_fused(const int* __restrict__ gI, const int* __restrict__ gJ, const int* __restrict__ gK,
               const float* __restrict__ A, const float* __restrict__ Bm, const float* __restrict__ Cm,
               const float* __restrict__ W0, const float* __restrict__ b0,
               const float* __restrict__ W1, const float* __restrict__ b1,
               const float* __restrict__ W2, const float* __restrict__ b2,
               const float* __restrict__ W3, const float* __restrict__ b3,
               const float* __restrict__ FCW, const float* __restrict__ FCB,
               float* __restrict__ out, int n)
{
    __shared__ alignas(16) float sm[SMF];

    const int tid  = threadIdx.x;
    const int lane = tid & 31;
    const int wrp  = tid >> 5;

    // ---- prologue: weights into registers ----
    // w1p: layer1, warp = 4-channel K-slice [4wrp,4wrp+4), lane = f.
    //   w1p[tap]   = pack(W1[f][4wrp+0][tap], W1[f][4wrp+1][tap])
    //   w1p[8+tap] = pack(W1[f][4wrp+2][tap], W1[f][4wrp+3][tap])
    unsigned long long w1p[16];
    STAGE_STORE(W1);
    __syncthreads();
#pragma unroll
    for (int t = 0; t < 8; ++t) {
        w1p[t]     = packf2(sm[(t * 32 + 4 * wrp + 0) * 33 + lane],
                            sm[(t * 32 + 4 * wrp + 1) * 33 + lane]);
        w1p[8 + t] = packf2(sm[(t * 32 + 4 * wrp + 2) * 33 + lane],
                            sm[(t * 32 + 4 * wrp + 3) * 33 + lane]);
    }
    __syncthreads();

    // w2r/w3r: shfl scheme, warp = position (t1 / q2), lane = f.
    //   w2r[c] = W2[f=lane][c][t1=wrp]
    float w2r[32], w3r[32];
    STAGE_STORE(W2);
    __syncthreads();
#pragma unroll
    for (int c = 0; c < 32; ++c) w2r[c] = sm[(wrp * 32 + c) * 33 + lane];
    __syncthreads();
    STAGE_STORE(W3);
    __syncthreads();
#pragma unroll
    for (int c = 0; c < 32; ++c) w3r[c] = sm[(wrp * 32 + c) * 33 + lane];

    float w0r[8];
#pragma unroll
    for (int t = 0; t < 8; ++t) w0r[t] = W0[lane * 8 + t];
    const float bias0 = b0[lane], bias1 = b1[lane], bias2 = b2[lane], bias3 = b3[lane];
    const float fcw = FCW[lane], fcb = FCB[0];

    const int wd = (wrp >> 2) & 1, wh = (wrp >> 1) & 1, ww = wrp & 1;

    const int ebase = blockIdx.x * EPC;
    for (int e0 = 0; e0 < EPC; ++e0) {
        const int e = ebase + e0;
        if (e >= n) break;             // uniform across CTA
        __syncthreads();               // staging / previous-element boundary

        // ---- gather a, b, c rows ----
        if (tid < 48) {
            const int which = tid >> 4, idx = tid & 15;
            const int row = (which == 0) ? gI[e] : (which == 1 ? gJ[e] : gK[e]);
            const float* src = (which == 0) ? A : (which == 1 ? Bm : Cm);
            sm[S_ABC + tid] = src[row * 16 + idx];
        }
        __syncthreads();

        // ---- BC outer product + WA (W0 pre-contracted with a-pairs) ----
        sm[S_BC + tid] = sm[S_ABC + 16 + (tid >> 4)] * sm[S_ABC + 32 + (tid & 15)];
        {
            const float a0 = sm[S_ABC + 2 * wrp], a1 = sm[S_ABC + 2 * wrp + 1];
            ((float4*)(sm + S_WA))[wrp * 32 + lane] = make_float4(
                fmaf(w0r[0], a0, w0r[4] * a1),
                fmaf(w0r[1], a0, w0r[5] * a1),
                fmaf(w0r[2], a0, w0r[6] * a1),
                fmaf(w0r[3], a0, w0r[7] * a1));
        }
        __syncthreads();

        // ---- depth-first over the 8 layer-2 cells ----
#pragma unroll
        for (int q2 = 0; q2 < 8; ++q2) {
            const int d2 = (q2 >> 2) & 1, h2 = (q2 >> 1) & 1, w2b = q2 & 1;
            const int D1 = 2 * d2 + wd, H1 = 2 * h2 + wh, Wd1 = 2 * w2b + ww;

            // layer0: thread (t1 = wrp, c = lane) produces 8 taps into s_y0
            const float4 wa0 = ((const float4*)(sm + S_WA))[(2 * D1) * 32 + lane];
            const float4 wa1 = ((const float4*)(sm + S_WA))[(2 * D1 + 1) * 32 + lane];
#pragma unroll
            for (int qh = 0; qh < 2; ++qh) {
                const float4 bcA = *(const float4*)&sm[S_BC + (4 * H1 + 2 * qh) * 16 + 4 * Wd1];
                const float4 bcB = *(const float4*)&sm[S_BC + (4 * H1 + 2 * qh + 1) * 16 + 4 * Wd1];
                float v;
                v = fmaf(wa0.x, bcA.x, fmaf(wa0.y, bcA.y, fmaf(wa0.z, bcB.x, fmaf(wa0.w, bcB.y, bias0))));
                sm[S_Y0 + (wrp * 8 + qh * 2 + 0) * 32 + lane] = fmaxf(v, 0.f);
                v = fmaf(wa0.x, bcA.z, fmaf(wa0.y, bcA.w, fmaf(wa0.z, bcB.z, fmaf(wa0.w, bcB.w, bias0))));
                sm[S_Y0 + (wrp * 8 + qh * 2 + 1) * 32 + lane] = fmaxf(v, 0.f);
                v = fmaf(wa1.x, bcA.x, fmaf(wa1.y, bcA.y, fmaf(wa1.z, bcB.x, fmaf(wa1.w, bcB.y, bias0))));
                sm[S_Y0 + (wrp * 8 + 4 + qh * 2 + 0) * 32 + lane] = fmaxf(v, 0.f);
                v = fmaf(wa1.x, bcA.z, fmaf(wa1.y, bcA.w, fmaf(wa1.z, bcB.z, fmaf(wa1.w, bcB.w, bias0))));
                sm[S_Y0 + (wrp * 8 + 4 + qh * 2 + 1) * 32 + lane] = fmaxf(v, 0.f);
            }
            __syncthreads();

            // layer1 partials: warp's 4-channel slice, 8 positions, packed f32x2
#pragma unroll
            for (int t1 = 0; t1 < 8; ++t1) {
                unsigned long long a01 = 0ull, a23 = 0ull;
#pragma unroll
                for (int tap = 0; tap < 8; ++tap) {
                    const ulonglong2 vv =
                        *(const ulonglong2*)&sm[S_Y0 + (t1 * 8 + tap) * 32 + 4 * wrp];
                    a01 = ffma2(w1p[tap],     vv.x, a01);
                    a23 = ffma2(w1p[8 + tap], vv.y, a23);
                }
                const float2 f01 = unpackf2(a01), f23 = unpackf2(a23);
                sm[S_P1 + (t1 * 8 + wrp) * 32 + lane] = (f01.x + f23.x) + (f01.y + f23.y);
            }
            __syncthreads();

            // y1 reduce -> register (thread: t1 = wrp, x = lane)
            float s = sm[S_P1 + (wrp * 8 + 0) * 32 + lane];
#pragma unroll
            for (int wi = 1; wi < 8; ++wi) s += sm[S_P1 + (wrp * 8 + wi) * 32 + lane];
            const float y1reg = fmaxf(s + bias1, 0.f);

            // layer2 partial via shfl-broadcast: warp wrp = t1 slice, lane = f
            {
                float acc0 = 0.f, acc1 = 0.f;
#pragma unroll
                for (int c = 0; c < 32; c += 2) {
                    const float x0 = __shfl_sync(0xffffffffu, y1reg, c);
                    const float x1 = __shfl_sync(0xffffffffu, y1reg, c + 1);
                    acc0 = fmaf(w2r[c],     x0, acc0);
                    acc1 = fmaf(w2r[c + 1], x1, acc1);
                }
                sm[S_P2 + (q2 * 8 + wrp) * 32 + lane] = acc0 + acc1;
            }
        }
        __syncthreads();

        // y2 reduce -> register (thread: q2 = wrp, x = lane)
        float s2 = sm[S_P2 + (wrp * 8 + 0) * 32 + lane];
#pragma unroll
        for (int wi = 1; wi < 8; ++wi) s2 += sm[S_P2 + (wrp * 8 + wi) * 32 + lane];
        const float y2reg = fmaxf(s2 + bias2, 0.f);

        // layer3 partial via shfl-broadcast: warp wrp = q2 slice, lane = f
        {
            float acc0 = 0.f, acc1 = 0.f;
#pragma unroll
            for (int c = 0; c < 32; c += 2) {
                const float x0 = __shfl_sync(0xffffffffu, y2reg, c);
                const float x1 = __shfl_sync(0xffffffffu, y2reg, c + 1);
                acc0 = fmaf(w3r[c],     x0, acc0);
                acc1 = fmaf(w3r[c + 1], x1, acc1);
            }
            sm[S_P3 + wrp * 32 + lane] = acc0 + acc1;
        }
        __syncthreads();

        // final reduce + fc + sigmoid
        if (wrp == 0) {
            float s3 = sm[S_P3 + lane];
#pragma unroll
            for (int wi = 1; wi < 8; ++wi) s3 += sm[S_P3 + wi * 32 + lane];
            const float y3 = fmaxf(s3 + bias3, 0.f);
            float v = fcw * y3;
#pragma unroll
            for (int off = 16; off; off >>= 1)
                v += __shfl_xor_sync(0xffffffffu, v, off);
            if (lane == 0)
                out[e] = 1.0f / (1.0f + __expf(-(v + fcb)));
        }
    }
}

extern "C" void kernel_launch(void* const* d_in, const int* in_sizes, int n_in,
                              void* d_out, int out_size) {
    const int*   gI  = (const int*)d_in[0];
    const int*   gJ  = (const int*)d_in[1];
    const int*   gK  = (const int*)d_in[2];
    const float* A   = (const float*)d_in[3];
    const float* B   = (const float*)d_in[4];
    const float* C   = (const float*)d_in[5];
    const float* W0  = (const float*)d_in[6];
    const float* b0  = (const float*)d_in[7];
    const float* W1  = (const float*)d_in[8];
    const float* b1  = (const float*)d_in[9];
    const float* W2  = (const float*)d_in[10];
    const float* b2  = (const float*)d_in[11];
    const float* W3  = (const float*)d_in[12];
    const float* b3  = (const float*)d_in[13];
    const float* FCW = (const float*)d_in[14];
    const float* FCB = (const float*)d_in[15];

    const int n = in_sizes[0];
    const int grid = (n + EPC - 1) / EPC;
    ntc_fused<<<grid, 256>>>(gI, gJ, gK, A, B, C, W0, b0, W1, b1, W2, b2,
                             W3, b3, FCW, FCB, (float*)d_out, n);
}

// round 6
// speedup vs baseline: 1.8357x; 1.8357x over previous
#include <cuda_runtime.h>
#include <cstdint>

#define EPC 8
// float offsets in dynamic smem
#define S_ABC 0
#define S_BC  64
#define S_WA  320
#define S_BH  1344   // [pos 8][kp stride 132] packed bf16x2 hi
#define S_BL  2400   // lo
#define S_P1  3456   // [warp 8][16 x stride10]
#define S_Y1  4736   // [pos][f]
#define S_P2  4992   // [q2*8+w][f]
#define S_Y2  7040
#define S_P3  7296
#define S_W3S 8448   // [c*8+q][f] 8192 floats (persistent; stage buffer = 0..8448)
#define SMF   16640
#define SMEM_BYTES (SMF * 4)

__device__ __forceinline__ uint32_t pack_bf16x2(float lo, float hi) {
    uint32_t d;
    asm("cvt.rn.bf16x2.f32 %0, %1, %2;" : "=r"(d) : "f"(hi), "f"(lo));
    return d;
}
__device__ __forceinline__ float bf_lo(uint32_t v) { return __uint_as_float(v << 16); }
__device__ __forceinline__ float bf_hi(uint32_t v) { return __uint_as_float(v & 0xffff0000u); }
__device__ __forceinline__ void split2(float v0, float v1, uint32_t& h, uint32_t& l) {
    h = pack_bf16x2(v0, v1);
    l = pack_bf16x2(v0 - bf_lo(h), v1 - bf_hi(h));
}
__device__ __forceinline__ void mma_bf16(float& c0, float& c1, float& c2, float& c3,
                                         uint32_t a0, uint32_t a1, uint32_t a2, uint32_t a3,
                                         uint32_t b0, uint32_t b1) {
    asm("mma.sync.aligned.m16n8k16.row.col.f32.bf16.bf16.f32 "
        "{%0,%1,%2,%3},{%4,%5,%6,%7},{%8,%9},{%0,%1,%2,%3};"
        : "+f"(c0), "+f"(c1), "+f"(c2), "+f"(c3)
        : "r"(a0), "r"(a1), "r"(a2), "r"(a3), "r"(b0), "r"(b1));
}

// scatter Wsrc ([f=32][c=32][t=8]) into transposed padded smem: sm[(t*32+c)*33+f]
#define STAGE_STORE(Wsrc) do {                                              \
    _Pragma("unroll")                                                       \
    for (int r = 0; r < 8; ++r) {                                           \
        int i4 = tid + 256 * r;                                             \
        float4 v = ((const float4*)(Wsrc))[i4];                             \
        int f = i4 >> 6, rem = i4 & 63, c = rem >> 1, tb = (rem & 1) * 4;   \
        sm[((tb + 0) * 32 + c) * 33 + f] = v.x;                             \
        sm[((tb + 1) * 32 + c) * 33 + f] = v.y;                             \
        sm[((tb + 2) * 32 + c) * 33 + f] = v.z;                             \
        sm[((tb + 3) * 32 + c) * 33 + f] = v.w;                             \
    }                                                                       \
} while (0)

__global__ __launch_bounds__(256, 2)
void ntc_fused(const int* __restrict__ gI, const int* __restrict__ gJ, const int* __restrict__ gK,
               const float* __restrict__ A, const float* __restrict__ Bm, const float* __restrict__ Cm,
               const float* __restrict__ W0, const float* __restrict__ b0,
               const float* __restrict__ W1, const float* __restrict__ b1,
               const float* __restrict__ W2, const float* __restrict__ b2,
               const float* __restrict__ W3, const float* __restrict__ b3,
               const float* __restrict__ FCW, const float* __restrict__ FCB,
               float* __restrict__ out, int n)
{
    extern __shared__ float sm[];
    uint32_t* smu = (uint32_t*)sm;

    const int tid  = threadIdx.x;
    const int lane = tid & 31;
    const int wrp  = tid >> 5;
    const int tig  = lane & 3;      // thread-in-group (mma)
    const int gid  = lane >> 2;     // group id (mma)
    const int mt   = wrp & 1;       // m-tile (16 filters)
    const int kq   = wrp >> 1;      // K-quarter (64 of 256)

    // ---- A fragments for layer1: W1[f][k], k = c*8+tap == linear index. bf16 hi/lo split ----
    uint32_t ah[16], al[16];
#pragma unroll
    for (int ch = 0; ch < 4; ++ch)
#pragma unroll
        for (int r = 0; r < 4; ++r) {
            const int fr = mt * 16 + gid + (r & 1) * 8;
            const int k  = kq * 64 + ch * 16 + (r >> 1) * 8 + 2 * tig;
            const float2 w = *(const float2*)&W1[fr * 256 + k];
            split2(w.x, w.y, ah[ch * 4 + r], al[ch * 4 + r]);
        }

    // ---- W2 into regs via staged transpose: w2r[cp*8+t1] = W2[f=lane][4wrp+cp][t1] ----
    float w2r[32];
    STAGE_STORE(W2);
    __syncthreads();
#pragma unroll
    for (int cp = 0; cp < 4; ++cp)
#pragma unroll
        for (int t = 0; t < 8; ++t)
            w2r[cp * 8 + t] = sm[(t * 32 + 4 * wrp + cp) * 33 + lane];

    // ---- W3 into persistent smem: w3s[(c*8+q)*32 + f] (region disjoint from stage buffer) ----
#pragma unroll
    for (int r = 0; r < 32; ++r) {
        const int idx = tid + 256 * r;
        sm[S_W3S + (idx & 255) * 32 + (idx >> 8)] = W3[idx];
    }

    float w0r[8];
#pragma unroll
    for (int t = 0; t < 8; ++t) w0r[t] = W0[lane * 8 + t];
    const float bias0 = b0[lane], bias1 = b1[lane], bias2 = b2[lane], bias3 = b3[lane];
    const float fcw = FCW[lane], fcb = FCB[0];

    const int wd = (wrp >> 2) & 1, wh = (wrp >> 1) & 1, ww = wrp & 1;

    const int ebase = blockIdx.x * EPC;
    for (int e0 = 0; e0 < EPC; ++e0) {
        const int e = ebase + e0;
        if (e >= n) break;             // uniform across CTA
        __syncthreads();               // prologue / previous-element boundary

        // ---- gather a, b, c rows ----
        if (tid < 48) {
            const int which = tid >> 4, idx = tid & 15;
            const int row = (which == 0) ? gI[e] : (which == 1 ? gJ[e] : gK[e]);
            const float* src = (which == 0) ? A : (which == 1 ? Bm : Cm);
            sm[S_ABC + tid] = src[row * 16 + idx];
        }
        __syncthreads();

        // ---- BC outer product + WA (W0 pre-contracted with a-pairs) ----
        sm[S_BC + tid] = sm[S_ABC + 16 + (tid >> 4)] * sm[S_ABC + 32 + (tid & 15)];
        {
            const float a0 = sm[S_ABC + 2 * wrp], a1 = sm[S_ABC + 2 * wrp + 1];
            ((float4*)(sm + S_WA))[wrp * 32 + lane] = make_float4(
                fmaf(w0r[0], a0, w0r[4] * a1),
                fmaf(w0r[1], a0, w0r[5] * a1),
                fmaf(w0r[2], a0, w0r[6] * a1),
                fmaf(w0r[3], a0, w0r[7] * a1));
        }
        __syncthreads();

        // ---- depth-first over the 8 layer-2 cells ----
        for (int q2 = 0; q2 < 8; ++q2) {
            const int d2 = (q2 >> 2) & 1, h2 = (q2 >> 1) & 1, w2b = q2 & 1;
            const int D1 = 2 * d2 + wd, H1 = 2 * h2 + wh, Wd1 = 2 * w2b + ww;

            // layer0: thread (pos = wrp, c = lane) produces 8 taps -> bf16 hi/lo packed B tiles
            const float4 wa0 = ((const float4*)(sm + S_WA))[(2 * D1) * 32 + lane];
            const float4 wa1 = ((const float4*)(sm + S_WA))[(2 * D1 + 1) * 32 + lane];
            float v[8];
#pragma unroll
            for (int qh = 0; qh < 2; ++qh) {
                const float4 bcA = *(const float4*)&sm[S_BC + (4 * H1 + 2 * qh) * 16 + 4 * Wd1];
                const float4 bcB = *(const float4*)&sm[S_BC + (4 * H1 + 2 * qh + 1) * 16 + 4 * Wd1];
                v[qh * 2 + 0] = fmaxf(fmaf(wa0.x, bcA.x, fmaf(wa0.y, bcA.y, fmaf(wa0.z, bcB.x, fmaf(wa0.w, bcB.y, bias0)))), 0.f);
                v[qh * 2 + 1] = fmaxf(fmaf(wa0.x, bcA.z, fmaf(wa0.y, bcA.w, fmaf(wa0.z, bcB.z, fmaf(wa0.w, bcB.w, bias0)))), 0.f);
                v[4 + qh * 2 + 0] = fmaxf(fmaf(wa1.x, bcA.x, fmaf(wa1.y, bcA.y, fmaf(wa1.z, bcB.x, fmaf(wa1.w, bcB.y, bias0)))), 0.f);
                v[4 + qh * 2 + 1] = fmaxf(fmaf(wa1.x, bcA.z, fmaf(wa1.y, bcA.w, fmaf(wa1.z, bcB.z, fmaf(wa1.w, bcB.w, bias0)))), 0.f);
            }
            uint32_t hv[4], lv[4];
#pragma unroll
            for (int p = 0; p < 4; ++p) split2(v[2 * p], v[2 * p + 1], hv[p], lv[p]);
            // B layout [pos][kp], kp = c*4+p, row stride 132 words; STS.128, conflict-free
            *(uint4*)&smu[S_BH + wrp * 132 + 4 * lane] = make_uint4(hv[0], hv[1], hv[2], hv[3]);
            *(uint4*)&smu[S_BL + wrp * 132 + 4 * lane] = make_uint4(lv[0], lv[1], lv[2], lv[3]);
            __syncthreads();

            // layer1 MMA: warp = (m-tile mt, K-quarter kq); D[16f x 8pos] partial
            float c0 = 0.f, c1 = 0.f, c2 = 0.f, c3 = 0.f;
#pragma unroll
            for (int ch = 0; ch < 4; ++ch) {
                const int bb = gid * 132 + kq * 32 + ch * 8 + tig;
                const uint32_t bh0 = smu[S_BH + bb], bh1 = smu[S_BH + bb + 4];
                const uint32_t bl0 = smu[S_BL + bb], bl1 = smu[S_BL + bb + 4];
                mma_bf16(c0, c1, c2, c3, ah[ch*4+0], ah[ch*4+1], ah[ch*4+2], ah[ch*4+3], bh0, bh1);
                mma_bf16(c0, c1, c2, c3, ah[ch*4+0], ah[ch*4+1], ah[ch*4+2], ah[ch*4+3], bl0, bl1);
                mma_bf16(c0, c1, c2, c3, al[ch*4+0], al[ch*4+1], al[ch*4+2], al[ch*4+3], bh0, bh1);
            }
            {
                float* p = sm + S_P1 + wrp * 160 + gid * 10 + 2 * tig;
                *(float2*)p        = make_float2(c0, c1);
                *(float2*)(p + 80) = make_float2(c2, c3);
            }
            __syncthreads();

            // reduce 4 K-quarters -> y1[pos][f]  (thread: pos = wrp, f = lane)
            {
                float s = 0.f;
#pragma unroll
                for (int kqi = 0; kqi < 4; ++kqi)
                    s += sm[S_P1 + (kqi * 2 + (lane >> 4)) * 160 + (lane & 15) * 10 + wrp];
                sm[S_Y1 + wrp * 32 + lane] = fmaxf(s + bias1, 0.f);
            }
            __syncthreads();

            // layer2 partial (SIMT, weights in regs): warp = 4-channel slice, lane = f
            {
                float accA = 0.f, accB = 0.f;
#pragma unroll
                for (int t1 = 0; t1 < 8; ++t1) {
                    const float4 y1v = *(const float4*)&sm[S_Y1 + t1 * 32 + 4 * wrp];
                    accA = fmaf(w2r[t1],      y1v.x, accA);
                    accB = fmaf(w2r[8 + t1],  y1v.y, accB);
                    accA = fmaf(w2r[16 + t1], y1v.z, accA);
                    accB = fmaf(w2r[24 + t1], y1v.w, accB);
                }
                sm[S_P2 + (q2 * 8 + wrp) * 32 + lane] = accA + accB;
            }
        }
        __syncthreads();

        // y2 reduce (thread: q2 = wrp, f = lane)
        {
            float s2 = sm[S_P2 + (wrp * 8 + 0) * 32 + lane];
#pragma unroll
            for (int wi = 1; wi < 8; ++wi) s2 += sm[S_P2 + (wrp * 8 + wi) * 32 + lane];
            sm[S_Y2 + wrp * 32 + lane] = fmaxf(s2 + bias2, 0.f);
        }
        __syncthreads();

        // layer3 partial: warp = 4-channel slice, lane = f; weights from persistent smem
        {
            float acc = 0.f;
#pragma unroll
            for (int q2 = 0; q2 < 8; ++q2) {
                const float4 y2v = *(const float4*)&sm[S_Y2 + q2 * 32 + 4 * wrp];
                const float w30 = sm[S_W3S + ((4 * wrp + 0) * 8 + q2) * 32 + lane];
                const float w31 = sm[S_W3S + ((4 * wrp + 1) * 8 + q2) * 32 + lane];
                const float w32 = sm[S_W3S + ((4 * wrp + 2) * 8 + q2) * 32 + lane];
                const float w33 = sm[S_W3S + ((4 * wrp + 3) * 8 + q2) * 32 + lane];
                acc = fmaf(w30, y2v.x, acc);
                acc = fmaf(w31, y2v.y, acc);
                acc = fmaf(w32, y2v.z, acc);
                acc = fmaf(w33, y2v.w, acc);
            }
            sm[S_P3 + wrp * 32 + lane] = acc;
        }
        __syncthreads();

        // final reduce + fc + sigmoid
        if (wrp == 0) {
            float s3 = sm[S_P3 + lane];
#pragma unroll
            for (int wi = 1; wi < 8; ++wi) s3 += sm[S_P3 + wi * 32 + lane];
            const float y3 = fmaxf(s3 + bias3, 0.f);
            float vv = fcw * y3;
#pragma unroll
            for (int off = 16; off; off >>= 1)
                vv += __shfl_xor_sync(0xffffffffu, vv, off);
            if (lane == 0)
                out[e] = 1.0f / (1.0f + __expf(-(vv + fcb)));
        }
    }
}

extern "C" void kernel_launch(void* const* d_in, const int* in_sizes, int n_in,
                              void* d_out, int out_size) {
    const int*   gI  = (const int*)d_in[0];
    const int*   gJ  = (const int*)d_in[1];
    const int*   gK  = (const int*)d_in[2];
    const float* A   = (const float*)d_in[3];
    const float* B   = (const float*)d_in[4];
    const float* C   = (const float*)d_in[5];
    const float* W0  = (const float*)d_in[6];
    const float* b0  = (const float*)d_in[7];
    const float* W1  = (const float*)d_in[8];
    const float* b1  = (const float*)d_in[9];
    const float* W2  = (const float*)d_in[10];
    const float* b2  = (const float*)d_in[11];
    const float* W3  = (const float*)d_in[12];
    const float* b3  = (const float*)d_in[13];
    const float* FCW = (const float*)d_in[14];
    const float* FCB = (const float*)d_in[15];

    cudaFuncSetAttribute(ntc_fused, cudaFuncAttributeMaxDynamicSharedMemorySize, SMEM_BYTES);

    const int n = in_sizes[0];
    const int grid = (n + EPC - 1) / EPC;
    ntc_fused<<<grid, 256, SMEM_BYTES>>>(gI, gJ, gK, A, B, C, W0, b0, W1, b1, W2, b2,
                                         W3, b3, FCW, FCB, (float*)d_out, n);
}

// round 7
// speedup vs baseline: 2.0468x; 1.1150x over previous
#include <cuda_runtime.h>
#include <cstdint>

#define EPC 8
// word offsets in dynamic smem
#define S_B1H 0        // [n=32 rows][132] packed bf16x2 hi   (stage buffer overlays 0..8448)
#define S_B1L 4224     // lo
#define S_ABC 8448
#define S_BC  8512
#define S_WA  8768     // float4[8][32]
#define S_P1  9792     // 8 warps x 673 (odd stride => conflict-free reduce)
#define P1WS  673
#define S_Y1  15176    // [q2i 4][t1 8][f 32] fp32
#define S_P2  16200    // [q2*8+w][f]
#define S_Y2  18248
#define S_P3  18504
#define S_W3S 18760    // [k 256][f 32]
#define SMW   26952
#define SMEM_BYTES (SMW * 4)

__device__ __forceinline__ uint32_t pack_bf16x2(float lo, float hi) {
    uint32_t d;
    asm("cvt.rn.bf16x2.f32 %0, %1, %2;" : "=r"(d) : "f"(hi), "f"(lo));
    return d;
}
__device__ __forceinline__ float bf_lo(uint32_t v) { return __uint_as_float(v << 16); }
__device__ __forceinline__ float bf_hi(uint32_t v) { return __uint_as_float(v & 0xffff0000u); }
__device__ __forceinline__ void split2(float v0, float v1, uint32_t& h, uint32_t& l) {
    h = pack_bf16x2(v0, v1);
    l = pack_bf16x2(v0 - bf_lo(h), v1 - bf_hi(h));
}
__device__ __forceinline__ void mma_bf16(float& c0, float& c1, float& c2, float& c3,
                                         uint32_t a0, uint32_t a1, uint32_t a2, uint32_t a3,
                                         uint32_t b0, uint32_t b1) {
    asm("mma.sync.aligned.m16n8k16.row.col.f32.bf16.bf16.f32 "
        "{%0,%1,%2,%3},{%4,%5,%6,%7},{%8,%9},{%0,%1,%2,%3};"
        : "+f"(c0), "+f"(c1), "+f"(c2), "+f"(c3)
        : "r"(a0), "r"(a1), "r"(a2), "r"(a3), "r"(b0), "r"(b1));
}

// scatter Wsrc ([f=32][c=32][t=8]) into transposed padded smem at offset 0: sm[(t*32+c)*33+f]
#define STAGE_STORE(Wsrc) do {                                              \
    _Pragma("unroll")                                                       \
    for (int r = 0; r < 8; ++r) {                                           \
        int i4 = tid + 256 * r;                                             \
        float4 v = ((const float4*)(Wsrc))[i4];                             \
        int f = i4 >> 6, rem = i4 & 63, c = rem >> 1, tb = (rem & 1) * 4;   \
        sm[((tb + 0) * 32 + c) * 33 + f] = v.x;                             \
        sm[((tb + 1) * 32 + c) * 33 + f] = v.y;                             \
        sm[((tb + 2) * 32 + c) * 33 + f] = v.z;                             \
        sm[((tb + 3) * 32 + c) * 33 + f] = v.w;                             \
    }                                                                       \
} while (0)

__global__ __launch_bounds__(256, 2)
void ntc_fused(const int* __restrict__ gI, const int* __restrict__ gJ, const int* __restrict__ gK,
               const float* __restrict__ A, const float* __restrict__ Bm, const float* __restrict__ Cm,
               const float* __restrict__ W0, const float* __restrict__ b0,
               const float* __restrict__ W1, const float* __restrict__ b1,
               const float* __restrict__ W2, const float* __restrict__ b2,
               const float* __restrict__ W3, const float* __restrict__ b3,
               const float* __restrict__ FCW, const float* __restrict__ FCB,
               float* __restrict__ out, int n)
{
    extern __shared__ float sm[];
    uint32_t* smu = (uint32_t*)sm;

    const int tid  = threadIdx.x;
    const int lane = tid & 31;
    const int wrp  = tid >> 5;
    const int tig  = lane & 3;
    const int gid  = lane >> 2;
    const int mt   = wrp & 1;     // m-tile (16 filters)
    const int kq   = wrp >> 1;    // K-quarter (64 of 256)

    // ---- A fragments for layer1 mma (bf16 hi/lo split of W1) ----
    uint32_t ah[16], al[16];
#pragma unroll
    for (int ch = 0; ch < 4; ++ch)
#pragma unroll
        for (int r = 0; r < 4; ++r) {
            const int fr = mt * 16 + gid + (r & 1) * 8;
            const int k  = kq * 64 + ch * 16 + (r >> 1) * 8 + 2 * tig;
            const float2 w = *(const float2*)&W1[fr * 256 + k];
            split2(w.x, w.y, ah[ch * 4 + r], al[ch * 4 + r]);
        }

    // ---- W2 into regs via staged transpose (stage buffer overlays B1 region) ----
    float w2r[32];
    STAGE_STORE(W2);
    __syncthreads();
#pragma unroll
    for (int cp = 0; cp < 4; ++cp)
#pragma unroll
        for (int t = 0; t < 8; ++t)
            w2r[cp * 8 + t] = sm[(t * 32 + 4 * wrp + cp) * 33 + lane];

    // ---- W3 into persistent smem: [k=c*8+q][f] ----
#pragma unroll
    for (int r = 0; r < 32; ++r) {
        const int idx = tid + 256 * r;
        sm[S_W3S + (idx & 255) * 32 + (idx >> 8)] = W3[idx];
    }

    float w0r[8];
#pragma unroll
    for (int t = 0; t < 8; ++t) w0r[t] = W0[lane * 8 + t];
    const float bias0 = b0[lane], bias1 = b1[lane], bias2 = b2[lane], bias3 = b3[lane];
    const float fcw = FCW[lane], fcb = FCB[0];

    const int wd = (wrp >> 2) & 1, wh = (wrp >> 1) & 1, ww = wrp & 1;
    // reduce-phase thread mapping
    const int rf   = tid & 31;            // filter
    const int rt1g = (tid >> 5) & 1;      // t1 half (0..3 / 4..7)
    const int rq2i = tid >> 6;            // q2 within half
    const int rmt = rf >> 4, rrow = rf & 15;
    const int rbase_off = (rrow & 7) * 10 + (rrow >> 3) * 80 + rq2i * 168 + rt1g * 4;

    const int ebase = blockIdx.x * EPC;
    for (int e0 = 0; e0 < EPC; ++e0) {
        const int e = ebase + e0;
        if (e >= n) break;            // uniform across CTA
        __syncthreads();              // prologue / previous-element boundary

        // ---- gather a, b, c rows ----
        if (tid < 48) {
            const int which = tid >> 4, idx = tid & 15;
            const int row = (which == 0) ? gI[e] : (which == 1 ? gJ[e] : gK[e]);
            const float* src = (which == 0) ? A : (which == 1 ? Bm : Cm);
            sm[S_ABC + tid] = src[row * 16 + idx];
        }
        __syncthreads();

        // ---- BC outer product + WA ----
        sm[S_BC + tid] = sm[S_ABC + 16 + (tid >> 4)] * sm[S_ABC + 32 + (tid & 15)];
        {
            const float a0 = sm[S_ABC + 2 * wrp], a1 = sm[S_ABC + 2 * wrp + 1];
            ((float4*)(sm + S_WA))[wrp * 32 + lane] = make_float4(
                fmaf(w0r[0], a0, w0r[4] * a1),
                fmaf(w0r[1], a0, w0r[5] * a1),
                fmaf(w0r[2], a0, w0r[6] * a1),
                fmaf(w0r[3], a0, w0r[7] * a1));
        }
        __syncthreads();

        // ---- two d2-halves, each batching 4 q2-cells through one mma pass ----
#pragma unroll
        for (int half = 0; half < 2; ++half) {
            // layer0: wa pair constant across the half (D1 = 2*half + wd)
            const int D1 = 2 * half + wd;
            const float4 wa0 = ((const float4*)(sm + S_WA))[(2 * D1) * 32 + lane];
            const float4 wa1 = ((const float4*)(sm + S_WA))[(2 * D1 + 1) * 32 + lane];
#pragma unroll
            for (int q2i = 0; q2i < 4; ++q2i) {
                const int H1 = 2 * (q2i >> 1) + wh, Wd1 = 2 * (q2i & 1) + ww;
                float v[8];
#pragma unroll
                for (int qh = 0; qh < 2; ++qh) {
                    const float4 bcA = *(const float4*)&sm[S_BC + (4 * H1 + 2 * qh) * 16 + 4 * Wd1];
                    const float4 bcB = *(const float4*)&sm[S_BC + (4 * H1 + 2 * qh + 1) * 16 + 4 * Wd1];
                    v[qh*2+0]   = fmaxf(fmaf(wa0.x, bcA.x, fmaf(wa0.y, bcA.y, fmaf(wa0.z, bcB.x, fmaf(wa0.w, bcB.y, bias0)))), 0.f);
                    v[qh*2+1]   = fmaxf(fmaf(wa0.x, bcA.z, fmaf(wa0.y, bcA.w, fmaf(wa0.z, bcB.z, fmaf(wa0.w, bcB.w, bias0)))), 0.f);
                    v[4+qh*2+0] = fmaxf(fmaf(wa1.x, bcA.x, fmaf(wa1.y, bcA.y, fmaf(wa1.z, bcB.x, fmaf(wa1.w, bcB.y, bias0)))), 0.f);
                    v[4+qh*2+1] = fmaxf(fmaf(wa1.x, bcA.z, fmaf(wa1.y, bcA.w, fmaf(wa1.z, bcB.z, fmaf(wa1.w, bcB.w, bias0)))), 0.f);
                }
                uint32_t hv[4], lv[4];
#pragma unroll
                for (int p = 0; p < 4; ++p) split2(v[2*p], v[2*p+1], hv[p], lv[p]);
                const int rowoff = (q2i * 8 + wrp) * 132 + 4 * lane;
                *(uint4*)&smu[S_B1H + rowoff] = make_uint4(hv[0], hv[1], hv[2], hv[3]);
                *(uint4*)&smu[S_B1L + rowoff] = make_uint4(lv[0], lv[1], lv[2], lv[3]);
            }
            __syncthreads();

            // layer1 mma: warp = (mt, kq); 4 n-tiles of 8 positions
#pragma unroll
            for (int nt = 0; nt < 4; ++nt) {
                float c0 = 0.f, c1 = 0.f, c2 = 0.f, c3 = 0.f;
#pragma unroll
                for (int ch = 0; ch < 4; ++ch) {
                    const int bb = (nt * 8 + gid) * 132 + kq * 32 + ch * 8 + tig;
                    const uint32_t bh0 = smu[S_B1H + bb], bh1 = smu[S_B1H + bb + 4];
                    const uint32_t bl0 = smu[S_B1L + bb], bl1 = smu[S_B1L + bb + 4];
                    mma_bf16(c0, c1, c2, c3, ah[ch*4+0], ah[ch*4+1], ah[ch*4+2], ah[ch*4+3], bh0, bh1);
                    mma_bf16(c0, c1, c2, c3, ah[ch*4+0], ah[ch*4+1], ah[ch*4+2], ah[ch*4+3], bl0, bl1);
                    mma_bf16(c0, c1, c2, c3, al[ch*4+0], al[ch*4+1], al[ch*4+2], al[ch*4+3], bh0, bh1);
                }
                float* p = sm + S_P1 + wrp * P1WS + nt * 168 + gid * 10 + 2 * tig;
                p[0] = c0; p[1] = c1; p[80] = c2; p[81] = c3;
            }
            __syncthreads();

            // y1 reduce (4 K-quarters) -> Y1[q2i][t1][f]; conflict-free (odd P1WS)
            {
                float s0 = 0.f, s1 = 0.f, s2 = 0.f, s3 = 0.f;
#pragma unroll
                for (int kqi = 0; kqi < 4; ++kqi) {
                    const float* p = sm + S_P1 + (rmt + 2 * kqi) * P1WS + rbase_off;
                    s0 += p[0]; s1 += p[1]; s2 += p[2]; s3 += p[3];
                }
                float* y = sm + S_Y1 + rq2i * 256 + rt1g * 128 + rf;
                y[0]  = fmaxf(s0 + bias1, 0.f);
                y[32] = fmaxf(s1 + bias1, 0.f);
                y[64] = fmaxf(s2 + bias1, 0.f);
                y[96] = fmaxf(s3 + bias1, 0.f);
            }
            __syncthreads();

            // layer2 partials (SIMT): warp = 4-channel slice, lane = f
#pragma unroll
            for (int q2i = 0; q2i < 4; ++q2i) {
                float accA = 0.f, accB = 0.f;
#pragma unroll
                for (int t1 = 0; t1 < 8; ++t1) {
                    const float4 y1v = *(const float4*)&sm[S_Y1 + q2i * 256 + t1 * 32 + 4 * wrp];
                    accA = fmaf(w2r[t1],      y1v.x, accA);
                    accB = fmaf(w2r[8 + t1],  y1v.y, accB);
                    accA = fmaf(w2r[16 + t1], y1v.z, accA);
                    accB = fmaf(w2r[24 + t1], y1v.w, accB);
                }
                sm[S_P2 + ((half * 4 + q2i) * 8 + wrp) * 32 + lane] = accA + accB;
            }
        }
        __syncthreads();

        // y2 reduce (thread: q2 = wrp, f = lane)
        {
            float s2 = sm[S_P2 + (wrp * 8 + 0) * 32 + lane];
#pragma unroll
            for (int wi = 1; wi < 8; ++wi) s2 += sm[S_P2 + (wrp * 8 + wi) * 32 + lane];
            sm[S_Y2 + wrp * 32 + lane] = fmaxf(s2 + bias2, 0.f);
        }
        __syncthreads();

        // layer3 partial: warp = 4-channel slice, lane = f; weights from persistent smem
        {
            float acc = 0.f;
#pragma unroll
            for (int q2 = 0; q2 < 8; ++q2) {
                const float4 y2v = *(const float4*)&sm[S_Y2 + q2 * 32 + 4 * wrp];
                const float w30 = sm[S_W3S + ((4 * wrp + 0) * 8 + q2) * 32 + lane];
                const float w31 = sm[S_W3S + ((4 * wrp + 1) * 8 + q2) * 32 + lane];
                const float w32 = sm[S_W3S + ((4 * wrp + 2) * 8 + q2) * 32 + lane];
                const float w33 = sm[S_W3S + ((4 * wrp + 3) * 8 + q2) * 32 + lane];
                acc = fmaf(w30, y2v.x, acc);
                acc = fmaf(w31, y2v.y, acc);
                acc = fmaf(w32, y2v.z, acc);
                acc = fmaf(w33, y2v.w, acc);
            }
            sm[S_P3 + wrp * 32 + lane] = acc;
        }
        __syncthreads();

        // final reduce + fc + sigmoid
        if (wrp == 0) {
            float s3 = sm[S_P3 + lane];
#pragma unroll
            for (int wi = 1; wi < 8; ++wi) s3 += sm[S_P3 + wi * 32 + lane];
            const float y3 = fmaxf(s3 + bias3, 0.f);
            float vv = fcw * y3;
#pragma unroll
            for (int off = 16; off; off >>= 1)
                vv += __shfl_xor_sync(0xffffffffu, vv, off);
            if (lane == 0)
                out[e] = 1.0f / (1.0f + __expf(-(vv + fcb)));
        }
    }
}

extern "C" void kernel_launch(void* const* d_in, const int* in_sizes, int n_in,
                              void* d_out, int out_size) {
    const int*   gI  = (const int*)d_in[0];
    const int*   gJ  = (const int*)d_in[1];
    const int*   gK  = (const int*)d_in[2];
    const float* A   = (const float*)d_in[3];
    const float* B   = (const float*)d_in[4];
    const float* C   = (const float*)d_in[5];
    const float* W0  = (const float*)d_in[6];
    const float* b0  = (const float*)d_in[7];
    const float* W1  = (const float*)d_in[8];
    const float* b1  = (const float*)d_in[9];
    const float* W2  = (const float*)d_in[10];
    const float* b2  = (const float*)d_in[11];
    const float* W3  = (const float*)d_in[12];
    const float* b3  = (const float*)d_in[13];
    const float* FCW = (const float*)d_in[14];
    const float* FCB = (const float*)d_in[15];

    cudaFuncSetAttribute(ntc_fused, cudaFuncAttributeMaxDynamicSharedMemorySize, SMEM_BYTES);

    const int n = in_sizes[0];
    const int grid = (n + EPC - 1) / EPC;
    ntc_fused<<<grid, 256, SMEM_BYTES>>>(gI, gJ, gK, A, B, C, W0, b0, W1, b1, W2, b2,
                                         W3, b3, FCW, FCB, (float*)d_out, n);
}

// round 8
// speedup vs baseline: 2.2932x; 1.1204x over previous
#include <cuda_runtime.h>
#include <cstdint>

#define EPC 8
// word offsets in dynamic smem
#define S_B1H 0        // [n=32 rows][132] packed bf16x2 hi
#define S_B1L 4224     // lo
#define S_ABC 8448
#define S_BC  8512
#define S_WA  8768     // float4[8][32]
#define S_P1  9792     // 8 warps x 673
#define P1WS  673
#define S_P2  15176    // 8 warps x 169
#define P2WS  169
#define S_B2H 16528    // [q2 8][132] layer2 B, bf16x2 hi
#define S_B2L 17584
#define S_Y2  18640    // [q2][f]
#define S_P3  18896
#define S_W3S 19152    // [k 256][f 32]
#define SMW   27344
#define SMEM_BYTES (SMW * 4)

__device__ __forceinline__ uint32_t pack_bf16x2(float lo, float hi) {
    uint32_t d;
    asm("cvt.rn.bf16x2.f32 %0, %1, %2;" : "=r"(d) : "f"(hi), "f"(lo));
    return d;
}
__device__ __forceinline__ float bf_lo(uint32_t v) { return __uint_as_float(v << 16); }
__device__ __forceinline__ float bf_hi(uint32_t v) { return __uint_as_float(v & 0xffff0000u); }
__device__ __forceinline__ void split2(float v0, float v1, uint32_t& h, uint32_t& l) {
    h = pack_bf16x2(v0, v1);
    l = pack_bf16x2(v0 - bf_lo(h), v1 - bf_hi(h));
}
__device__ __forceinline__ void mma_bf16(float& c0, float& c1, float& c2, float& c3,
                                         uint32_t a0, uint32_t a1, uint32_t a2, uint32_t a3,
                                         uint32_t b0, uint32_t b1) {
    asm("mma.sync.aligned.m16n8k16.row.col.f32.bf16.bf16.f32 "
        "{%0,%1,%2,%3},{%4,%5,%6,%7},{%8,%9},{%0,%1,%2,%3};"
        : "+f"(c0), "+f"(c1), "+f"(c2), "+f"(c3)
        : "r"(a0), "r"(a1), "r"(a2), "r"(a3), "r"(b0), "r"(b1));
}
__device__ __forceinline__ void ldm4(uint32_t& r0, uint32_t& r1, uint32_t& r2, uint32_t& r3,
                                     uint32_t saddr) {
    asm volatile("ldmatrix.sync.aligned.m8n8.x4.shared.b16 {%0,%1,%2,%3}, [%4];"
                 : "=r"(r0), "=r"(r1), "=r"(r2), "=r"(r3) : "r"(saddr));
}

__global__ __launch_bounds__(256, 2)
void ntc_fused(const int* __restrict__ gI, const int* __restrict__ gJ, const int* __restrict__ gK,
               const float* __restrict__ A, const float* __restrict__ Bm, const float* __restrict__ Cm,
               const float* __restrict__ W0, const float* __restrict__ b0,
               const float* __restrict__ W1, const float* __restrict__ b1,
               const float* __restrict__ W2, const float* __restrict__ b2,
               const float* __restrict__ W3, const float* __restrict__ b3,
               const float* __restrict__ FCW, const float* __restrict__ FCB,
               float* __restrict__ out, int n)
{
    extern __shared__ float sm[];
    uint32_t* smu = (uint32_t*)sm;
    const uint32_t smbase = (uint32_t)__cvta_generic_to_shared(sm);

    const int tid  = threadIdx.x;
    const int lane = tid & 31;
    const int wrp  = tid >> 5;
    const int tig  = lane & 3;
    const int gid  = lane >> 2;
    const int mt   = wrp & 1;     // m-tile (16 filters)
    const int kq   = wrp >> 1;    // K-quarter (64 of 256)

    // ---- A fragments for layer1 AND layer2 mma (bf16 hi/lo split; k = linear W index) ----
    uint32_t a1h[16], a1l[16], a2h[16], a2l[16];
#pragma unroll
    for (int ch = 0; ch < 4; ++ch)
#pragma unroll
        for (int r = 0; r < 4; ++r) {
            const int fr = mt * 16 + gid + (r & 1) * 8;
            const int k  = kq * 64 + ch * 16 + (r >> 1) * 8 + 2 * tig;
            const float2 w1v = *(const float2*)&W1[fr * 256 + k];
            split2(w1v.x, w1v.y, a1h[ch * 4 + r], a1l[ch * 4 + r]);
            const float2 w2v = *(const float2*)&W2[fr * 256 + k];
            split2(w2v.x, w2v.y, a2h[ch * 4 + r], a2l[ch * 4 + r]);
        }

    // ---- W3 into persistent smem: [k=c*8+q][f] ----
#pragma unroll
    for (int r = 0; r < 32; ++r) {
        const int idx = tid + 256 * r;
        sm[S_W3S + (idx & 255) * 32 + (idx >> 8)] = W3[idx];
    }

    float w0r[8];
#pragma unroll
    for (int t = 0; t < 8; ++t) w0r[t] = W0[lane * 8 + t];
    const float bias0 = b0[lane], bias1 = b1[lane], bias2 = b2[lane], bias3 = b3[lane];
    const float fcw = FCW[lane], fcb = FCB[0];

    const int wd = (wrp >> 2) & 1, wh = (wrp >> 1) & 1, ww = wrp & 1;
    // y1-reduce mapping (P1 -> B2)
    const int rf   = tid & 31;          // filter/channel c
    const int rt1g = (tid >> 5) & 1;    // t1 group of 4
    const int rq2i = tid >> 6;          // q2 within half
    const int rmt = rf >> 4, rrow = rf & 15;
    const int rbase_off = (rrow & 7) * 10 + (rrow >> 3) * 80 + rq2i * 168 + rt1g * 4;
    // y2-reduce mapping (P2 -> Y2); active tid<64
    const int yc = tid & 31, yq2g = (tid >> 5) & 1;
    const int ymt = yc >> 4, yr16 = yc & 15;
    const int yoff = (yr16 & 7) * 10 + (yr16 >> 3) * 80 + 4 * yq2g;

    const int ebase = blockIdx.x * EPC;
    for (int e0 = 0; e0 < EPC; ++e0) {
        const int e = ebase + e0;
        if (e >= n) break;            // uniform across CTA
        __syncthreads();              // prologue / previous-element boundary

        // ---- gather a, b, c rows ----
        if (tid < 48) {
            const int which = tid >> 4, idx = tid & 15;
            const int row = (which == 0) ? gI[e] : (which == 1 ? gJ[e] : gK[e]);
            const float* src = (which == 0) ? A : (which == 1 ? Bm : Cm);
            sm[S_ABC + tid] = src[row * 16 + idx];
        }
        __syncthreads();

        // ---- BC outer product + WA ----
        sm[S_BC + tid] = sm[S_ABC + 16 + (tid >> 4)] * sm[S_ABC + 32 + (tid & 15)];
        {
            const float a0 = sm[S_ABC + 2 * wrp], a1 = sm[S_ABC + 2 * wrp + 1];
            ((float4*)(sm + S_WA))[wrp * 32 + lane] = make_float4(
                fmaf(w0r[0], a0, w0r[4] * a1),
                fmaf(w0r[1], a0, w0r[5] * a1),
                fmaf(w0r[2], a0, w0r[6] * a1),
                fmaf(w0r[3], a0, w0r[7] * a1));
        }
        __syncthreads();

        // ---- two d2-halves ----
#pragma unroll
        for (int half = 0; half < 2; ++half) {
            // layer0: thread (pos = wrp, c = lane) -> B1 rows q2i*8+wrp
            const int D1 = 2 * half + wd;
            const float4 wa0 = ((const float4*)(sm + S_WA))[(2 * D1) * 32 + lane];
            const float4 wa1 = ((const float4*)(sm + S_WA))[(2 * D1 + 1) * 32 + lane];
#pragma unroll
            for (int q2i = 0; q2i < 4; ++q2i) {
                const int H1 = 2 * (q2i >> 1) + wh, Wd1 = 2 * (q2i & 1) + ww;
                float v[8];
#pragma unroll
                for (int qh = 0; qh < 2; ++qh) {
                    const float4 bcA = *(const float4*)&sm[S_BC + (4 * H1 + 2 * qh) * 16 + 4 * Wd1];
                    const float4 bcB = *(const float4*)&sm[S_BC + (4 * H1 + 2 * qh + 1) * 16 + 4 * Wd1];
                    v[qh*2+0]   = fmaxf(fmaf(wa0.x, bcA.x, fmaf(wa0.y, bcA.y, fmaf(wa0.z, bcB.x, fmaf(wa0.w, bcB.y, bias0)))), 0.f);
                    v[qh*2+1]   = fmaxf(fmaf(wa0.x, bcA.z, fmaf(wa0.y, bcA.w, fmaf(wa0.z, bcB.z, fmaf(wa0.w, bcB.w, bias0)))), 0.f);
                    v[4+qh*2+0] = fmaxf(fmaf(wa1.x, bcA.x, fmaf(wa1.y, bcA.y, fmaf(wa1.z, bcB.x, fmaf(wa1.w, bcB.y, bias0)))), 0.f);
                    v[4+qh*2+1] = fmaxf(fmaf(wa1.x, bcA.z, fmaf(wa1.y, bcA.w, fmaf(wa1.z, bcB.z, fmaf(wa1.w, bcB.w, bias0)))), 0.f);
                }
                uint32_t hv[4], lv[4];
#pragma unroll
                for (int p = 0; p < 4; ++p) split2(v[2*p], v[2*p+1], hv[p], lv[p]);
                const int rowoff = (q2i * 8 + wrp) * 132 + 4 * lane;
                *(uint4*)&smu[S_B1H + rowoff] = make_uint4(hv[0], hv[1], hv[2], hv[3]);
                *(uint4*)&smu[S_B1L + rowoff] = make_uint4(lv[0], lv[1], lv[2], lv[3]);
            }
            __syncthreads();

            // layer1 mma: B via ldmatrix.x4 (4 k-slabs per instr)
#pragma unroll
            for (int nt = 0; nt < 4; ++nt) {
                const uint32_t rowb = (uint32_t)(((nt * 8 + (lane & 7)) * 132 + kq * 32 + ((lane >> 3) << 2)) * 4);
                uint32_t h0,h1,h2,h3,h4,h5,h6,h7, l0,l1,l2,l3,l4,l5,l6,l7;
                ldm4(h0,h1,h2,h3, smbase + S_B1H*4 + rowb);
                ldm4(h4,h5,h6,h7, smbase + S_B1H*4 + rowb + 64);
                ldm4(l0,l1,l2,l3, smbase + S_B1L*4 + rowb);
                ldm4(l4,l5,l6,l7, smbase + S_B1L*4 + rowb + 64);
                float c0 = 0.f, c1 = 0.f, c2 = 0.f, c3 = 0.f;
                mma_bf16(c0,c1,c2,c3, a1h[0],a1h[1],a1h[2],a1h[3],     h0,h1);
                mma_bf16(c0,c1,c2,c3, a1h[0],a1h[1],a1h[2],a1h[3],     l0,l1);
                mma_bf16(c0,c1,c2,c3, a1l[0],a1l[1],a1l[2],a1l[3],     h0,h1);
                mma_bf16(c0,c1,c2,c3, a1h[4],a1h[5],a1h[6],a1h[7],     h2,h3);
                mma_bf16(c0,c1,c2,c3, a1h[4],a1h[5],a1h[6],a1h[7],     l2,l3);
                mma_bf16(c0,c1,c2,c3, a1l[4],a1l[5],a1l[6],a1l[7],     h2,h3);
                mma_bf16(c0,c1,c2,c3, a1h[8],a1h[9],a1h[10],a1h[11],   h4,h5);
                mma_bf16(c0,c1,c2,c3, a1h[8],a1h[9],a1h[10],a1h[11],   l4,l5);
                mma_bf16(c0,c1,c2,c3, a1l[8],a1l[9],a1l[10],a1l[11],   h4,h5);
                mma_bf16(c0,c1,c2,c3, a1h[12],a1h[13],a1h[14],a1h[15], h6,h7);
                mma_bf16(c0,c1,c2,c3, a1h[12],a1h[13],a1h[14],a1h[15], l6,l7);
                mma_bf16(c0,c1,c2,c3, a1l[12],a1l[13],a1l[14],a1l[15], h6,h7);
                float* p = sm + S_P1 + wrp * P1WS + nt * 168 + gid * 10 + 2 * tig;
                p[0] = c0; p[1] = c1; p[80] = c2; p[81] = c3;
            }
            __syncthreads();

            // y1 reduce -> B2 rows (bf16 hi/lo, k2 = c*8 + t1)
            {
                float s0 = 0.f, s1 = 0.f, s2 = 0.f, s3 = 0.f;
#pragma unroll
                for (int kqi = 0; kqi < 4; ++kqi) {
                    const float* p = sm + S_P1 + (rmt + 2 * kqi) * P1WS + rbase_off;
                    s0 += p[0]; s1 += p[1]; s2 += p[2]; s3 += p[3];
                }
                const float y0 = fmaxf(s0 + bias1, 0.f);
                const float y1v = fmaxf(s1 + bias1, 0.f);
                const float y2v = fmaxf(s2 + bias1, 0.f);
                const float y3v = fmaxf(s3 + bias1, 0.f);
                uint32_t h0, l0, h1, l1;
                split2(y0, y1v, h0, l0);
                split2(y2v, y3v, h1, l1);
                const int q2 = half * 4 + rq2i;
                const int kp = rf * 4 + rt1g * 2;
                *(uint2*)&smu[S_B2H + q2 * 132 + kp] = make_uint2(h0, h1);
                *(uint2*)&smu[S_B2L + q2 * 132 + kp] = make_uint2(l0, l1);
            }
            __syncthreads();
        }

        // ---- layer2 mma: D[16f x 8q2] partials per (mt, kq) warp ----
        {
            const uint32_t rowb = (uint32_t)((((lane & 7)) * 132 + kq * 32 + ((lane >> 3) << 2)) * 4);
            uint32_t h0,h1,h2,h3,h4,h5,h6,h7, l0,l1,l2,l3,l4,l5,l6,l7;
            ldm4(h0,h1,h2,h3, smbase + S_B2H*4 + rowb);
            ldm4(h4,h5,h6,h7, smbase + S_B2H*4 + rowb + 64);
            ldm4(l0,l1,l2,l3, smbase + S_B2L*4 + rowb);
            ldm4(l4,l5,l6,l7, smbase + S_B2L*4 + rowb + 64);
            float c0 = 0.f, c1 = 0.f, c2 = 0.f, c3 = 0.f;
            mma_bf16(c0,c1,c2,c3, a2h[0],a2h[1],a2h[2],a2h[3],     h0,h1);
            mma_bf16(c0,c1,c2,c3, a2h[0],a2h[1],a2h[2],a2h[3],     l0,l1);
            mma_bf16(c0,c1,c2,c3, a2l[0],a2l[1],a2l[2],a2l[3],     h0,h1);
            mma_bf16(c0,c1,c2,c3, a2h[4],a2h[5],a2h[6],a2h[7],     h2,h3);
            mma_bf16(c0,c1,c2,c3, a2h[4],a2h[5],a2h[6],a2h[7],     l2,l3);
            mma_bf16(c0,c1,c2,c3, a2l[4],a2l[5],a2l[6],a2l[7],     h2,h3);
            mma_bf16(c0,c1,c2,c3, a2h[8],a2h[9],a2h[10],a2h[11],   h4,h5);
            mma_bf16(c0,c1,c2,c3, a2h[8],a2h[9],a2h[10],a2h[11],   l4,l5);
            mma_bf16(c0,c1,c2,c3, a2l[8],a2l[9],a2l[10],a2l[11],   h4,h5);
            mma_bf16(c0,c1,c2,c3, a2h[12],a2h[13],a2h[14],a2h[15], h6,h7);
            mma_bf16(c0,c1,c2,c3, a2h[12],a2h[13],a2h[14],a2h[15], l6,l7);
            mma_bf16(c0,c1,c2,c3, a2l[12],a2l[13],a2l[14],a2l[15], h6,h7);
            float* p = sm + S_P2 + wrp * P2WS + gid * 10 + 2 * tig;
            p[0] = c0; p[1] = c1; p[80] = c2; p[81] = c3;
        }
        __syncthreads();

        // y2 reduce -> Y2[q2][f]
        if (tid < 64) {
            float s0 = 0.f, s1 = 0.f, s2 = 0.f, s3 = 0.f;
#pragma unroll
            for (int kqi = 0; kqi < 4; ++kqi) {
                const float* p = sm + S_P2 + (ymt + 2 * kqi) * P2WS + yoff;
                s0 += p[0]; s1 += p[1]; s2 += p[2]; s3 += p[3];
            }
            sm[S_Y2 + (4 * yq2g + 0) * 32 + yc] = fmaxf(s0 + bias2, 0.f);
            sm[S_Y2 + (4 * yq2g + 1) * 32 + yc] = fmaxf(s1 + bias2, 0.f);
            sm[S_Y2 + (4 * yq2g + 2) * 32 + yc] = fmaxf(s2 + bias2, 0.f);
            sm[S_Y2 + (4 * yq2g + 3) * 32 + yc] = fmaxf(s3 + bias2, 0.f);
        }
        __syncthreads();

        // layer3 partial (SIMT): warp = 4-channel slice, lane = f
        {
            float acc = 0.f;
#pragma unroll
            for (int q2 = 0; q2 < 8; ++q2) {
                const float4 y2v = *(const float4*)&sm[S_Y2 + q2 * 32 + 4 * wrp];
                const float w30 = sm[S_W3S + ((4 * wrp + 0) * 8 + q2) * 32 + lane];
                const float w31 = sm[S_W3S + ((4 * wrp + 1) * 8 + q2) * 32 + lane];
                const float w32 = sm[S_W3S + ((4 * wrp + 2) * 8 + q2) * 32 + lane];
                const float w33 = sm[S_W3S + ((4 * wrp + 3) * 8 + q2) * 32 + lane];
                acc = fmaf(w30, y2v.x, acc);
                acc = fmaf(w31, y2v.y, acc);
                acc = fmaf(w32, y2v.z, acc);
                acc = fmaf(w33, y2v.w, acc);
            }
            sm[S_P3 + wrp * 32 + lane] = acc;
        }
        __syncthreads();

        // final reduce + fc + sigmoid
        if (wrp == 0) {
            float s3 = sm[S_P3 + lane];
#pragma unroll
            for (int wi = 1; wi < 8; ++wi) s3 += sm[S_P3 + wi * 32 + lane];
            const float y3 = fmaxf(s3 + bias3, 0.f);
            float vv = fcw * y3;
#pragma unroll
            for (int off = 16; off; off >>= 1)
                vv += __shfl_xor_sync(0xffffffffu, vv, off);
            if (lane == 0)
                out[e] = 1.0f / (1.0f + __expf(-(vv + fcb)));
        }
    }
}

extern "C" void kernel_launch(void* const* d_in, const int* in_sizes, int n_in,
                              void* d_out, int out_size) {
    const int*   gI  = (const int*)d_in[0];
    const int*   gJ  = (const int*)d_in[1];
    const int*   gK  = (const int*)d_in[2];
    const float* A   = (const float*)d_in[3];
    const float* B   = (const float*)d_in[4];
    const float* C   = (const float*)d_in[5];
    const float* W0  = (const float*)d_in[6];
    const float* b0  = (const float*)d_in[7];
    const float* W1  = (const float*)d_in[8];
    const float* b1  = (const float*)d_in[9];
    const float* W2  = (const float*)d_in[10];
    const float* b2  = (const float*)d_in[11];
    const float* W3  = (const float*)d_in[12];
    const float* b3  = (const float*)d_in[13];
    const float* FCW = (const float*)d_in[14];
    const float* FCB = (const float*)d_in[15];

    cudaFuncSetAttribute(ntc_fused, cudaFuncAttributeMaxDynamicSharedMemorySize, SMEM_BYTES);

    const int n = in_sizes[0];
    const int grid = (n + EPC - 1) / EPC;
    ntc_fused<<<grid, 256, SMEM_BYTES>>>(gI, gJ, gK, A, B, C, W0, b0, W1, b1, W2, b2,
                                         W3, b3, FCW, FCB, (float*)d_out, n);
}

// round 9
// speedup vs baseline: 2.4055x; 1.0490x over previous
#include <cuda_runtime.h>
#include <cstdint>

#define EPC 8
// word offsets in dynamic smem
#define S_B1H 0        // [n=32 rows][132] packed bf16x2 hi
#define S_B1L 4224     // lo
#define S_ABC 8448
#define S_BC  8512
#define S_WA  8768     // float4[8][32]
#define S_P1  9792     // 8 warps x 580 ; row stride 8 + pad 4 per 4 rows, nt stride 144
#define P1WS  580
#define S_P2  14432    // 8 warps x 148
#define P2WS  148
#define S_B2H 15616    // [q2 8][132]
#define S_B2L 16672
#define S_Y2  17728    // [q2][f]
#define S_P3  17984
#define S_W3S 18240    // [q2][cq][f][4] : ((q2*8+cq)*32+f)*4+ci
#define SMW   26432
#define SMEM_BYTES (SMW * 4)

__device__ __forceinline__ uint32_t pack_bf16x2(float lo, float hi) {
    uint32_t d;
    asm("cvt.rn.bf16x2.f32 %0, %1, %2;" : "=r"(d) : "f"(hi), "f"(lo));
    return d;
}
__device__ __forceinline__ float bf_lo(uint32_t v) { return __uint_as_float(v << 16); }
__device__ __forceinline__ float bf_hi(uint32_t v) { return __uint_as_float(v & 0xffff0000u); }
__device__ __forceinline__ void split2(float v0, float v1, uint32_t& h, uint32_t& l) {
    h = pack_bf16x2(v0, v1);
    l = pack_bf16x2(v0 - bf_lo(h), v1 - bf_hi(h));
}
__device__ __forceinline__ void mma_bf16(float& c0, float& c1, float& c2, float& c3,
                                         uint32_t a0, uint32_t a1, uint32_t a2, uint32_t a3,
                                         uint32_t b0, uint32_t b1) {
    asm("mma.sync.aligned.m16n8k16.row.col.f32.bf16.bf16.f32 "
        "{%0,%1,%2,%3},{%4,%5,%6,%7},{%8,%9},{%0,%1,%2,%3};"
        : "+f"(c0), "+f"(c1), "+f"(c2), "+f"(c3)
        : "r"(a0), "r"(a1), "r"(a2), "r"(a3), "r"(b0), "r"(b1));
}
__device__ __forceinline__ void ldm4(uint32_t& r0, uint32_t& r1, uint32_t& r2, uint32_t& r3,
                                     uint32_t saddr) {
    asm volatile("ldmatrix.sync.aligned.m8n8.x4.shared.b16 {%0,%1,%2,%3}, [%4];"
                 : "=r"(r0), "=r"(r1), "=r"(r2), "=r"(r3) : "r"(saddr));
}

__global__ __launch_bounds__(256, 2)
void ntc_fused(const int* __restrict__ gI, const int* __restrict__ gJ, const int* __restrict__ gK,
               const float* __restrict__ A, const float* __restrict__ Bm, const float* __restrict__ Cm,
               const float* __restrict__ W0, const float* __restrict__ b0,
               const float* __restrict__ W1, const float* __restrict__ b1,
               const float* __restrict__ W2, const float* __restrict__ b2,
               const float* __restrict__ W3, const float* __restrict__ b3,
               const float* __restrict__ FCW, const float* __restrict__ FCB,
               float* __restrict__ out, int n)
{
    extern __shared__ float sm[];
    uint32_t* smu = (uint32_t*)sm;
    const uint32_t smbase = (uint32_t)__cvta_generic_to_shared(sm);

    const int tid  = threadIdx.x;
    const int lane = tid & 31;
    const int wrp  = tid >> 5;
    const int tig  = lane & 3;
    const int gid  = lane >> 2;
    const int mt   = wrp & 1;     // m-tile (16 filters)
    const int kq   = wrp >> 1;    // K-quarter (64 of 256)

    // ---- A fragments for layer1 AND layer2 mma (bf16 hi/lo split) ----
    uint32_t a1h[16], a1l[16], a2h[16], a2l[16];
#pragma unroll
    for (int ch = 0; ch < 4; ++ch)
#pragma unroll
        for (int r = 0; r < 4; ++r) {
            const int fr = mt * 16 + gid + (r & 1) * 8;
            const int k  = kq * 64 + ch * 16 + (r >> 1) * 8 + 2 * tig;
            const float2 w1v = *(const float2*)&W1[fr * 256 + k];
            split2(w1v.x, w1v.y, a1h[ch * 4 + r], a1l[ch * 4 + r]);
            const float2 w2v = *(const float2*)&W2[fr * 256 + k];
            split2(w2v.x, w2v.y, a2h[ch * 4 + r], a2l[ch * 4 + r]);
        }

    // ---- W3 into persistent smem as [q2][cq][f][4] for LDS.128 in layer3 ----
#pragma unroll
    for (int r = 0; r < 32; ++r) {
        const int idx = tid + 256 * r;            // = f*256 + c*8 + q2
        const int f = idx >> 8, c = (idx >> 3) & 31, q2 = idx & 7;
        sm[S_W3S + ((q2 * 8 + (c >> 2)) * 32 + f) * 4 + (c & 3)] = W3[idx];
    }

    float w0r[8];
#pragma unroll
    for (int t = 0; t < 8; ++t) w0r[t] = W0[lane * 8 + t];
    const float bias0 = b0[lane], bias1 = b1[lane], bias2 = b2[lane], bias3 = b3[lane];
    const float fcw = FCW[lane], fcb = FCB[0];

    const int wd = (wrp >> 2) & 1, wh = (wrp >> 1) & 1, ww = wrp & 1;
    // y1-reduce mapping
    const int rf   = tid & 31;          // channel c (output filter of layer1)
    const int rt1g = (tid >> 5) & 1;    // t1 group of 4
    const int rq2i = tid >> 6;          // q2 within half
    const int rmt = rf >> 4, r16 = rf & 15;
    const int rbase = S_P1 + rq2i * 144 + r16 * 8 + (r16 >> 2) * 4 + rt1g * 4;
    // y2-reduce mapping (tid<64)
    const int yc = tid & 31, yq2g = (tid >> 5) & 1;
    const int ymt = yc >> 4, yr16 = yc & 15;
    const int ybase = S_P2 + yr16 * 8 + (yr16 >> 2) * 4 + yq2g * 4;

    const int ebase = blockIdx.x * EPC;
    for (int e0 = 0; e0 < EPC; ++e0) {
        const int e = ebase + e0;
        if (e >= n) break;            // uniform across CTA
        __syncthreads();              // prologue / previous-element boundary

        // ---- gather a, b, c rows ----
        if (tid < 48) {
            const int which = tid >> 4, idx = tid & 15;
            const int row = (which == 0) ? gI[e] : (which == 1 ? gJ[e] : gK[e]);
            const float* src = (which == 0) ? A : (which == 1 ? Bm : Cm);
            sm[S_ABC + tid] = src[row * 16 + idx];
        }
        __syncthreads();

        // ---- BC outer product + WA ----
        sm[S_BC + tid] = sm[S_ABC + 16 + (tid >> 4)] * sm[S_ABC + 32 + (tid & 15)];
        {
            const float a0 = sm[S_ABC + 2 * wrp], a1 = sm[S_ABC + 2 * wrp + 1];
            ((float4*)(sm + S_WA))[wrp * 32 + lane] = make_float4(
                fmaf(w0r[0], a0, w0r[4] * a1),
                fmaf(w0r[1], a0, w0r[5] * a1),
                fmaf(w0r[2], a0, w0r[6] * a1),
                fmaf(w0r[3], a0, w0r[7] * a1));
        }
        __syncthreads();

        // ---- two d2-halves ----
#pragma unroll
        for (int half = 0; half < 2; ++half) {
            // layer0
            const int D1 = 2 * half + wd;
            const float4 wa0 = ((const float4*)(sm + S_WA))[(2 * D1) * 32 + lane];
            const float4 wa1 = ((const float4*)(sm + S_WA))[(2 * D1 + 1) * 32 + lane];
#pragma unroll
            for (int q2i = 0; q2i < 4; ++q2i) {
                const int H1 = 2 * (q2i >> 1) + wh, Wd1 = 2 * (q2i & 1) + ww;
                float v[8];
#pragma unroll
                for (int qh = 0; qh < 2; ++qh) {
                    const float4 bcA = *(const float4*)&sm[S_BC + (4 * H1 + 2 * qh) * 16 + 4 * Wd1];
                    const float4 bcB = *(const float4*)&sm[S_BC + (4 * H1 + 2 * qh + 1) * 16 + 4 * Wd1];
                    v[qh*2+0]   = fmaxf(fmaf(wa0.x, bcA.x, fmaf(wa0.y, bcA.y, fmaf(wa0.z, bcB.x, fmaf(wa0.w, bcB.y, bias0)))), 0.f);
                    v[qh*2+1]   = fmaxf(fmaf(wa0.x, bcA.z, fmaf(wa0.y, bcA.w, fmaf(wa0.z, bcB.z, fmaf(wa0.w, bcB.w, bias0)))), 0.f);
                    v[4+qh*2+0] = fmaxf(fmaf(wa1.x, bcA.x, fmaf(wa1.y, bcA.y, fmaf(wa1.z, bcB.x, fmaf(wa1.w, bcB.y, bias0)))), 0.f);
                    v[4+qh*2+1] = fmaxf(fmaf(wa1.x, bcA.z, fmaf(wa1.y, bcA.w, fmaf(wa1.z, bcB.z, fmaf(wa1.w, bcB.w, bias0)))), 0.f);
                }
                uint32_t hv[4], lv[4];
#pragma unroll
                for (int p = 0; p < 4; ++p) split2(v[2*p], v[2*p+1], hv[p], lv[p]);
                const int rowoff = (q2i * 8 + wrp) * 132 + 4 * lane;
                *(uint4*)&smu[S_B1H + rowoff] = make_uint4(hv[0], hv[1], hv[2], hv[3]);
                *(uint4*)&smu[S_B1L + rowoff] = make_uint4(lv[0], lv[1], lv[2], lv[3]);
            }
            __syncthreads();

            // layer1 mma
#pragma unroll
            for (int nt = 0; nt < 4; ++nt) {
                const uint32_t rowb = (uint32_t)(((nt * 8 + (lane & 7)) * 132 + kq * 32 + ((lane >> 3) << 2)) * 4);
                uint32_t h0,h1,h2,h3,h4,h5,h6,h7, l0,l1,l2,l3,l4,l5,l6,l7;
                ldm4(h0,h1,h2,h3, smbase + S_B1H*4 + rowb);
                ldm4(h4,h5,h6,h7, smbase + S_B1H*4 + rowb + 64);
                ldm4(l0,l1,l2,l3, smbase + S_B1L*4 + rowb);
                ldm4(l4,l5,l6,l7, smbase + S_B1L*4 + rowb + 64);
                float c0 = 0.f, c1 = 0.f, c2 = 0.f, c3 = 0.f;
                mma_bf16(c0,c1,c2,c3, a1h[0],a1h[1],a1h[2],a1h[3],     h0,h1);
                mma_bf16(c0,c1,c2,c3, a1h[0],a1h[1],a1h[2],a1h[3],     l0,l1);
                mma_bf16(c0,c1,c2,c3, a1l[0],a1l[1],a1l[2],a1l[3],     h0,h1);
                mma_bf16(c0,c1,c2,c3, a1h[4],a1h[5],a1h[6],a1h[7],     h2,h3);
                mma_bf16(c0,c1,c2,c3, a1h[4],a1h[5],a1h[6],a1h[7],     l2,l3);
                mma_bf16(c0,c1,c2,c3, a1l[4],a1l[5],a1l[6],a1l[7],     h2,h3);
                mma_bf16(c0,c1,c2,c3, a1h[8],a1h[9],a1h[10],a1h[11],   h4,h5);
                mma_bf16(c0,c1,c2,c3, a1h[8],a1h[9],a1h[10],a1h[11],   l4,l5);
                mma_bf16(c0,c1,c2,c3, a1l[8],a1l[9],a1l[10],a1l[11],   h4,h5);
                mma_bf16(c0,c1,c2,c3, a1h[12],a1h[13],a1h[14],a1h[15], h6,h7);
                mma_bf16(c0,c1,c2,c3, a1h[12],a1h[13],a1h[14],a1h[15], l6,l7);
                mma_bf16(c0,c1,c2,c3, a1l[12],a1l[13],a1l[14],a1l[15], h6,h7);
                // rows gid / gid+8, cols 2tig..2tig+1 : STS.64 pair
                float* p = sm + S_P1 + wrp * P1WS + nt * 144 + gid * 8 + (gid >> 2) * 4 + 2 * tig;
                *(float2*)p        = make_float2(c0, c1);
                *(float2*)(p + 72) = make_float2(c2, c3);
            }
            __syncthreads();

            // y1 reduce (LDS.128 over 4 K-quarters) -> B2 rows (bf16 hi/lo)
            {
                float s0 = 0.f, s1 = 0.f, s2 = 0.f, s3 = 0.f;
#pragma unroll
                for (int kqi = 0; kqi < 4; ++kqi) {
                    const float4 p = *(const float4*)&sm[rbase + (rmt + 2 * kqi) * P1WS];
                    s0 += p.x; s1 += p.y; s2 += p.z; s3 += p.w;
                }
                const float y0  = fmaxf(s0 + bias1, 0.f);
                const float y1v = fmaxf(s1 + bias1, 0.f);
                const float y2v = fmaxf(s2 + bias1, 0.f);
                const float y3v = fmaxf(s3 + bias1, 0.f);
                uint32_t h0, l0, h1, l1;
                split2(y0, y1v, h0, l0);
                split2(y2v, y3v, h1, l1);
                const int q2 = half * 4 + rq2i;
                const int kp = rf * 4 + rt1g * 2;
                *(uint2*)&smu[S_B2H + q2 * 132 + kp] = make_uint2(h0, h1);
                *(uint2*)&smu[S_B2L + q2 * 132 + kp] = make_uint2(l0, l1);
            }
            __syncthreads();
        }

        // ---- layer2 mma ----
        {
            const uint32_t rowb = (uint32_t)((((lane & 7)) * 132 + kq * 32 + ((lane >> 3) << 2)) * 4);
            uint32_t h0,h1,h2,h3,h4,h5,h6,h7, l0,l1,l2,l3,l4,l5,l6,l7;
            ldm4(h0,h1,h2,h3, smbase + S_B2H*4 + rowb);
            ldm4(h4,h5,h6,h7, smbase + S_B2H*4 + rowb + 64);
            ldm4(l0,l1,l2,l3, smbase + S_B2L*4 + rowb);
            ldm4(l4,l5,l6,l7, smbase + S_B2L*4 + rowb + 64);
            float c0 = 0.f, c1 = 0.f, c2 = 0.f, c3 = 0.f;
            mma_bf16(c0,c1,c2,c3, a2h[0],a2h[1],a2h[2],a2h[3],     h0,h1);
            mma_bf16(c0,c1,c2,c3, a2h[0],a2h[1],a2h[2],a2h[3],     l0,l1);
            mma_bf16(c0,c1,c2,c3, a2l[0],a2l[1],a2l[2],a2l[3],     h0,h1);
            mma_bf16(c0,c1,c2,c3, a2h[4],a2h[5],a2h[6],a2h[7],     h2,h3);
            mma_bf16(c0,c1,c2,c3, a2h[4],a2h[5],a2h[6],a2h[7],     l2,l3);
            mma_bf16(c0,c1,c2,c3, a2l[4],a2l[5],a2l[6],a2l[7],     h2,h3);
            mma_bf16(c0,c1,c2,c3, a2h[8],a2h[9],a2h[10],a2h[11],   h4,h5);
            mma_bf16(c0,c1,c2,c3, a2h[8],a2h[9],a2h[10],a2h[11],   l4,l5);
            mma_bf16(c0,c1,c2,c3, a2l[8],a2l[9],a2l[10],a2l[11],   h4,h5);
            mma_bf16(c0,c1,c2,c3, a2h[12],a2h[13],a2h[14],a2h[15], h6,h7);
            mma_bf16(c0,c1,c2,c3, a2h[12],a2h[13],a2h[14],a2h[15], l6,l7);
            mma_bf16(c0,c1,c2,c3, a2l[12],a2l[13],a2l[14],a2l[15], h6,h7);
            float* p = sm + S_P2 + wrp * P2WS + gid * 8 + (gid >> 2) * 4 + 2 * tig;
            *(float2*)p        = make_float2(c0, c1);
            *(float2*)(p + 72) = make_float2(c2, c3);
        }
        __syncthreads();

        // y2 reduce -> Y2[q2][f]
        if (tid < 64) {
            float s0 = 0.f, s1 = 0.f, s2 = 0.f, s3 = 0.f;
#pragma unroll
            for (int kqi = 0; kqi < 4; ++kqi) {
                const float4 p = *(const float4*)&sm[ybase + (ymt + 2 * kqi) * P2WS];
                s0 += p.x; s1 += p.y; s2 += p.z; s3 += p.w;
            }
            sm[S_Y2 + (4 * yq2g + 0) * 32 + yc] = fmaxf(s0 + bias2, 0.f);
            sm[S_Y2 + (4 * yq2g + 1) * 32 + yc] = fmaxf(s1 + bias2, 0.f);
            sm[S_Y2 + (4 * yq2g + 2) * 32 + yc] = fmaxf(s2 + bias2, 0.f);
            sm[S_Y2 + (4 * yq2g + 3) * 32 + yc] = fmaxf(s3 + bias2, 0.f);
        }
        __syncthreads();

        // layer3 partial (SIMT, vectorized): warp = 4-channel slice, lane = f
        {
            float acc = 0.f;
#pragma unroll
            for (int q2 = 0; q2 < 8; ++q2) {
                const float4 y2v = *(const float4*)&sm[S_Y2 + q2 * 32 + 4 * wrp];
                const float4 w3v = *(const float4*)&sm[S_W3S + ((q2 * 8 + wrp) * 32 + lane) * 4];
                acc = fmaf(w3v.x, y2v.x, acc);
                acc = fmaf(w3v.y, y2v.y, acc);
                acc = fmaf(w3v.z, y2v.z, acc);
                acc = fmaf(w3v.w, y2v.w, acc);
            }
            sm[S_P3 + wrp * 32 + lane] = acc;
        }
        __syncthreads();

        // final reduce + fc + sigmoid
        if (wrp == 0) {
            float s3 = sm[S_P3 + lane];
#pragma unroll
            for (int wi = 1; wi < 8; ++wi) s3 += sm[S_P3 + wi * 32 + lane];
            const float y3 = fmaxf(s3 + bias3, 0.f);
            float vv = fcw * y3;
#pragma unroll
            for (int off = 16; off; off >>= 1)
                vv += __shfl_xor_sync(0xffffffffu, vv, off);
            if (lane == 0)
                out[e] = 1.0f / (1.0f + __expf(-(vv + fcb)));
        }
    }
}

extern "C" void kernel_launch(void* const* d_in, const int* in_sizes, int n_in,
                              void* d_out, int out_size) {
    const int*   gI  = (const int*)d_in[0];
    const int*   gJ  = (const int*)d_in[1];
    const int*   gK  = (const int*)d_in[2];
    const float* A   = (const float*)d_in[3];
    const float* B   = (const float*)d_in[4];
    const float* C   = (const float*)d_in[5];
    const float* W0  = (const float*)d_in[6];
    const float* b0  = (const float*)d_in[7];
    const float* W1  = (const float*)d_in[8];
    const float* b1  = (const float*)d_in[9];
    const float* W2  = (const float*)d_in[10];
    const float* b2  = (const float*)d_in[11];
    const float* W3  = (const float*)d_in[12];
    const float* b3  = (const float*)d_in[13];
    const float* FCW = (const float*)d_in[14];
    const float* FCB = (const float*)d_in[15];

    cudaFuncSetAttribute(ntc_fused, cudaFuncAttributeMaxDynamicSharedMemorySize, SMEM_BYTES);

    const int n = in_sizes[0];
    const int grid = (n + EPC - 1) / EPC;
    ntc_fused<<<grid, 256, SMEM_BYTES>>>(gI, gJ, gK, A, B, C, W0, b0, W1, b1, W2, b2,
                                         W3, b3, FCW, FCB, (float*)d_out, n);
}

// round 10
// speedup vs baseline: 2.4786x; 1.0304x over previous
#include <cuda_runtime.h>
#include <cstdint>

#define EPC 8
// word offsets in dynamic smem
#define S_B1H 0        // [n=32 rows][132] packed bf16x2 hi
#define S_B1L 4224     // lo
#define S_ABC 8448
#define S_BC  8512
#define S_WA  8768     // float4[8][32]
#define S_P1  9792     // 8 warps x 580 ; row stride 8 + pad 4 per 4 rows, nt stride 144
#define P1WS  580
#define S_P2  14432    // 8 warps x 148
#define P2WS  148
#define S_B2H 15616    // [q2 8][132]
#define S_B2L 16672
#define S_Y2  17728    // [q2][f]
#define S_P3  17984
#define S_W3S 18240    // [q2][cq][f][4]
#define SMW   26432
#define SMEM_BYTES (SMW * 4)

__device__ __forceinline__ uint32_t pack_bf16x2(float lo, float hi) {
    uint32_t d;
    asm("cvt.rn.bf16x2.f32 %0, %1, %2;" : "=r"(d) : "f"(hi), "f"(lo));
    return d;
}
__device__ __forceinline__ float bf_lo(uint32_t v) { return __uint_as_float(v << 16); }
__device__ __forceinline__ float bf_hi(uint32_t v) { return __uint_as_float(v & 0xffff0000u); }
__device__ __forceinline__ void split2(float v0, float v1, uint32_t& h, uint32_t& l) {
    h = pack_bf16x2(v0, v1);
    l = pack_bf16x2(v0 - bf_lo(h), v1 - bf_hi(h));
}
__device__ __forceinline__ void mma_bf16(float& c0, float& c1, float& c2, float& c3,
                                         uint32_t a0, uint32_t a1, uint32_t a2, uint32_t a3,
                                         uint32_t b0, uint32_t b1) {
    asm("mma.sync.aligned.m16n8k16.row.col.f32.bf16.bf16.f32 "
        "{%0,%1,%2,%3},{%4,%5,%6,%7},{%8,%9},{%0,%1,%2,%3};"
        : "+f"(c0), "+f"(c1), "+f"(c2), "+f"(c3)
        : "r"(a0), "r"(a1), "r"(a2), "r"(a3), "r"(b0), "r"(b1));
}
__device__ __forceinline__ void ldm4(uint32_t& r0, uint32_t& r1, uint32_t& r2, uint32_t& r3,
                                     uint32_t saddr) {
    asm volatile("ldmatrix.sync.aligned.m8n8.x4.shared.b16 {%0,%1,%2,%3}, [%4];"
                 : "=r"(r0), "=r"(r1), "=r"(r2), "=r"(r3) : "r"(saddr));
}

__global__ __launch_bounds__(256, 2)
void ntc_fused(const int* __restrict__ gI, const int* __restrict__ gJ, const int* __restrict__ gK,
               const float* __restrict__ A, const float* __restrict__ Bm, const float* __restrict__ Cm,
               const float* __restrict__ W0, const float* __restrict__ b0,
               const float* __restrict__ W1, const float* __restrict__ b1,
               const float* __restrict__ W2, const float* __restrict__ b2,
               const float* __restrict__ W3, const float* __restrict__ b3,
               const float* __restrict__ FCW, const float* __restrict__ FCB,
               float* __restrict__ out, int n)
{
    extern __shared__ float sm[];
    uint32_t* smu = (uint32_t*)sm;
    const uint32_t smbase = (uint32_t)__cvta_generic_to_shared(sm);

    const int tid  = threadIdx.x;
    const int lane = tid & 31;
    const int wrp  = tid >> 5;
    const int tig  = lane & 3;
    const int gid  = lane >> 2;
    const int mt   = wrp & 1;
    const int kq   = wrp >> 1;

    // ---- A fragments for layer1 AND layer2 mma (bf16 hi/lo split) ----
    uint32_t a1h[16], a1l[16], a2h[16], a2l[16];
#pragma unroll
    for (int ch = 0; ch < 4; ++ch)
#pragma unroll
        for (int r = 0; r < 4; ++r) {
            const int fr = mt * 16 + gid + (r & 1) * 8;
            const int k  = kq * 64 + ch * 16 + (r >> 1) * 8 + 2 * tig;
            const float2 w1v = *(const float2*)&W1[fr * 256 + k];
            split2(w1v.x, w1v.y, a1h[ch * 4 + r], a1l[ch * 4 + r]);
            const float2 w2v = *(const float2*)&W2[fr * 256 + k];
            split2(w2v.x, w2v.y, a2h[ch * 4 + r], a2l[ch * 4 + r]);
        }

    // ---- W3 into persistent smem as [q2][cq][f][4] ----
#pragma unroll
    for (int r = 0; r < 32; ++r) {
        const int idx = tid + 256 * r;            // = f*256 + c*8 + q2
        const int f = idx >> 8, c = (idx >> 3) & 31, q2 = idx & 7;
        sm[S_W3S + ((q2 * 8 + (c >> 2)) * 32 + f) * 4 + (c & 3)] = W3[idx];
    }

    float w0r[8];
#pragma unroll
    for (int t = 0; t < 8; ++t) w0r[t] = W0[lane * 8 + t];
    const float bias0 = b0[lane], bias1 = b1[lane], bias2 = b2[lane], bias3 = b3[lane];
    const float fcw = FCW[lane], fcb = FCB[0];

    const int wd = (wrp >> 2) & 1, wh = (wrp >> 1) & 1, ww = wrp & 1;
    // y1-reduce mapping
    const int rf   = tid & 31;
    const int rt1g = (tid >> 5) & 1;
    const int rq2i = tid >> 6;
    const int rmt = rf >> 4, r16 = rf & 15;
    const int rbase = S_P1 + rq2i * 144 + r16 * 8 + (r16 >> 2) * 4 + rt1g * 4;
    // y2-reduce mapping (tid<64)
    const int yc = tid & 31, yq2g = (tid >> 5) & 1;
    const int ymt = yc >> 4, yr16 = yc & 15;
    const int ybase = S_P2 + yr16 * 8 + (yr16 >> 2) * 4 + yq2g * 4;

    // ---- epilogue for a finished element (reads S_P3) ----
    auto do_final = [&](int eo) {
        float s3 = sm[S_P3 + lane];
#pragma unroll
        for (int wi = 1; wi < 8; ++wi) s3 += sm[S_P3 + wi * 32 + lane];
        const float y3 = fmaxf(s3 + bias3, 0.f);
        float vv = fcw * y3;
#pragma unroll
        for (int off = 16; off; off >>= 1)
            vv += __shfl_xor_sync(0xffffffffu, vv, off);
        if (lane == 0)
            out[eo] = 1.0f / (1.0f + __expf(-(vv + fcb)));
    };

    // ---- layer0 body for one d2-half: writes B1 rows ----
    auto layer0 = [&](int half) {
        const int D1 = 2 * half + wd;
        const float4 wa0 = ((const float4*)(sm + S_WA))[(2 * D1) * 32 + lane];
        const float4 wa1 = ((const float4*)(sm + S_WA))[(2 * D1 + 1) * 32 + lane];
#pragma unroll
        for (int q2i = 0; q2i < 4; ++q2i) {
            const int H1 = 2 * (q2i >> 1) + wh, Wd1 = 2 * (q2i & 1) + ww;
            float v[8];
#pragma unroll
            for (int qh = 0; qh < 2; ++qh) {
                const float4 bcA = *(const float4*)&sm[S_BC + (4 * H1 + 2 * qh) * 16 + 4 * Wd1];
                const float4 bcB = *(const float4*)&sm[S_BC + (4 * H1 + 2 * qh + 1) * 16 + 4 * Wd1];
                v[qh*2+0]   = fmaxf(fmaf(wa0.x, bcA.x, fmaf(wa0.y, bcA.y, fmaf(wa0.z, bcB.x, fmaf(wa0.w, bcB.y, bias0)))), 0.f);
                v[qh*2+1]   = fmaxf(fmaf(wa0.x, bcA.z, fmaf(wa0.y, bcA.w, fmaf(wa0.z, bcB.z, fmaf(wa0.w, bcB.w, bias0)))), 0.f);
                v[4+qh*2+0] = fmaxf(fmaf(wa1.x, bcA.x, fmaf(wa1.y, bcA.y, fmaf(wa1.z, bcB.x, fmaf(wa1.w, bcB.y, bias0)))), 0.f);
                v[4+qh*2+1] = fmaxf(fmaf(wa1.x, bcA.z, fmaf(wa1.y, bcA.w, fmaf(wa1.z, bcB.z, fmaf(wa1.w, bcB.w, bias0)))), 0.f);
            }
            uint32_t hv[4], lv[4];
#pragma unroll
            for (int p = 0; p < 4; ++p) split2(v[2*p], v[2*p+1], hv[p], lv[p]);
            const int rowoff = (q2i * 8 + wrp) * 132 + 4 * lane;
            *(uint4*)&smu[S_B1H + rowoff] = make_uint4(hv[0], hv[1], hv[2], hv[3]);
            *(uint4*)&smu[S_B1L + rowoff] = make_uint4(lv[0], lv[1], lv[2], lv[3]);
        }
    };

    // ---- layer1 mma pass: reads B1, writes P1 ----
    auto mma1 = [&]() {
#pragma unroll
        for (int nt = 0; nt < 4; ++nt) {
            const uint32_t rowb = (uint32_t)(((nt * 8 + (lane & 7)) * 132 + kq * 32 + ((lane >> 3) << 2)) * 4);
            uint32_t h0,h1,h2,h3,h4,h5,h6,h7, l0,l1,l2,l3,l4,l5,l6,l7;
            ldm4(h0,h1,h2,h3, smbase + S_B1H*4 + rowb);
            ldm4(h4,h5,h6,h7, smbase + S_B1H*4 + rowb + 64);
            ldm4(l0,l1,l2,l3, smbase + S_B1L*4 + rowb);
            ldm4(l4,l5,l6,l7, smbase + S_B1L*4 + rowb + 64);
            float c0 = 0.f, c1 = 0.f, c2 = 0.f, c3 = 0.f;
            mma_bf16(c0,c1,c2,c3, a1h[0],a1h[1],a1h[2],a1h[3],     h0,h1);
            mma_bf16(c0,c1,c2,c3, a1h[0],a1h[1],a1h[2],a1h[3],     l0,l1);
            mma_bf16(c0,c1,c2,c3, a1l[0],a1l[1],a1l[2],a1l[3],     h0,h1);
            mma_bf16(c0,c1,c2,c3, a1h[4],a1h[5],a1h[6],a1h[7],     h2,h3);
            mma_bf16(c0,c1,c2,c3, a1h[4],a1h[5],a1h[6],a1h[7],     l2,l3);
            mma_bf16(c0,c1,c2,c3, a1l[4],a1l[5],a1l[6],a1l[7],     h2,h3);
            mma_bf16(c0,c1,c2,c3, a1h[8],a1h[9],a1h[10],a1h[11],   h4,h5);
            mma_bf16(c0,c1,c2,c3, a1h[8],a1h[9],a1h[10],a1h[11],   l4,l5);
            mma_bf16(c0,c1,c2,c3, a1l[8],a1l[9],a1l[10],a1l[11],   h4,h5);
            mma_bf16(c0,c1,c2,c3, a1h[12],a1h[13],a1h[14],a1h[15], h6,h7);
            mma_bf16(c0,c1,c2,c3, a1h[12],a1h[13],a1h[14],a1h[15], l6,l7);
            mma_bf16(c0,c1,c2,c3, a1l[12],a1l[13],a1l[14],a1l[15], h6,h7);
            float* p = sm + S_P1 + wrp * P1WS + nt * 144 + gid * 8 + (gid >> 2) * 4 + 2 * tig;
            *(float2*)p        = make_float2(c0, c1);
            *(float2*)(p + 72) = make_float2(c2, c3);
        }
    };

    // ---- y1 reduce body: sums into s0..s3 ----
    auto reduce_sum = [&](float& s0, float& s1, float& s2, float& s3) {
        s0 = s1 = s2 = s3 = 0.f;
#pragma unroll
        for (int kqi = 0; kqi < 4; ++kqi) {
            const float4 p = *(const float4*)&sm[rbase + (rmt + 2 * kqi) * P1WS];
            s0 += p.x; s1 += p.y; s2 += p.z; s3 += p.w;
        }
    };
    auto reduce_emit = [&](int half, float s0, float s1, float s2, float s3) {
        const float y0  = fmaxf(s0 + bias1, 0.f);
        const float y1v = fmaxf(s1 + bias1, 0.f);
        const float y2v = fmaxf(s2 + bias1, 0.f);
        const float y3v = fmaxf(s3 + bias1, 0.f);
        uint32_t h0, l0, h1, l1;
        split2(y0, y1v, h0, l0);
        split2(y2v, y3v, h1, l1);
        const int q2 = half * 4 + rq2i;
        const int kp = rf * 4 + rt1g * 2;
        *(uint2*)&smu[S_B2H + q2 * 132 + kp] = make_uint2(h0, h1);
        *(uint2*)&smu[S_B2L + q2 * 132 + kp] = make_uint2(l0, l1);
    };

    const int ebase = blockIdx.x * EPC;
    int nel = n - ebase;
    if (nel <= 0) return;
    if (nel > EPC) nel = EPC;

    for (int e0 = 0; e0 < nel; ++e0) {
        const int e = ebase + e0;
        __syncthreads();   // prev element's P3 complete / smem reuse boundary

        // deferred epilogue of previous element (warp 0) || gather (warps 2-3)
        if (wrp == 0) {
            if (e0 > 0) do_final(e - 1);
        } else if (tid >= 64 && tid < 112) {
            const int t = tid - 64;
            const int which = t >> 4, idx = t & 15;
            const int row = (which == 0) ? gI[e] : (which == 1 ? gJ[e] : gK[e]);
            const float* src = (which == 0) ? A : (which == 1 ? Bm : Cm);
            sm[S_ABC + t] = src[row * 16 + idx];
        }
        __syncthreads();

        // BC outer product + WA
        sm[S_BC + tid] = sm[S_ABC + 16 + (tid >> 4)] * sm[S_ABC + 32 + (tid & 15)];
        {
            const float a0 = sm[S_ABC + 2 * wrp], a1 = sm[S_ABC + 2 * wrp + 1];
            ((float4*)(sm + S_WA))[wrp * 32 + lane] = make_float4(
                fmaf(w0r[0], a0, w0r[4] * a1),
                fmaf(w0r[1], a0, w0r[5] * a1),
                fmaf(w0r[2], a0, w0r[6] * a1),
                fmaf(w0r[3], a0, w0r[7] * a1));
        }
        __syncthreads();

        layer0(0);
        __syncthreads();

        mma1();
        __syncthreads();

        // merged phase: y1-reduce(half0) + layer0(half1)
        {
            float s0, s1, s2, s3;
            reduce_sum(s0, s1, s2, s3);   // reads P1 (half0)
            layer0(1);                    // writes B1 (safe: mma(h0) reads done)
            reduce_emit(0, s0, s1, s2, s3);
        }
        __syncthreads();

        mma1();
        __syncthreads();

        {
            float s0, s1, s2, s3;
            reduce_sum(s0, s1, s2, s3);
            reduce_emit(1, s0, s1, s2, s3);
        }
        __syncthreads();

        // layer2 mma
        {
            const uint32_t rowb = (uint32_t)((((lane & 7)) * 132 + kq * 32 + ((lane >> 3) << 2)) * 4);
            uint32_t h0,h1,h2,h3,h4,h5,h6,h7, l0,l1,l2,l3,l4,l5,l6,l7;
            ldm4(h0,h1,h2,h3, smbase + S_B2H*4 + rowb);
            ldm4(h4,h5,h6,h7, smbase + S_B2H*4 + rowb + 64);
            ldm4(l0,l1,l2,l3, smbase + S_B2L*4 + rowb);
            ldm4(l4,l5,l6,l7, smbase + S_B2L*4 + rowb + 64);
            float c0 = 0.f, c1 = 0.f, c2 = 0.f, c3 = 0.f;
            mma_bf16(c0,c1,c2,c3, a2h[0],a2h[1],a2h[2],a2h[3],     h0,h1);
            mma_bf16(c0,c1,c2,c3, a2h[0],a2h[1],a2h[2],a2h[3],     l0,l1);
            mma_bf16(c0,c1,c2,c3, a2l[0],a2l[1],a2l[2],a2l[3],     h0,h1);
            mma_bf16(c0,c1,c2,c3, a2h[4],a2h[5],a2h[6],a2h[7],     h2,h3);
            mma_bf16(c0,c1,c2,c3, a2h[4],a2h[5],a2h[6],a2h[7],     l2,l3);
            mma_bf16(c0,c1,c2,c3, a2l[4],a2l[5],a2l[6],a2l[7],     h2,h3);
            mma_bf16(c0,c1,c2,c3, a2h[8],a2h[9],a2h[10],a2h[11],   h4,h5);
            mma_bf16(c0,c1,c2,c3, a2h[8],a2h[9],a2h[10],a2h[11],   l4,l5);
            mma_bf16(c0,c1,c2,c3, a2l[8],a2l[9],a2l[10],a2l[11],   h4,h5);
            mma_bf16(c0,c1,c2,c3, a2h[12],a2h[13],a2h[14],a2h[15], h6,h7);
            mma_bf16(c0,c1,c2,c3, a2h[12],a2h[13],a2h[14],a2h[15], l6,l7);
            mma_bf16(c0,c1,c2,c3, a2l[12],a2l[13],a2l[14],a2l[15], h6,h7);
            float* p = sm + S_P2 + wrp * P2WS + gid * 8 + (gid >> 2) * 4 + 2 * tig;
            *(float2*)p        = make_float2(c0, c1);
            *(float2*)(p + 72) = make_float2(c2, c3);
        }
        __syncthreads();

        // y2 reduce -> Y2[q2][f]
        if (tid < 64) {
            float s0 = 0.f, s1 = 0.f, s2 = 0.f, s3 = 0.f;
#pragma unroll
            for (int kqi = 0; kqi < 4; ++kqi) {
                const float4 p = *(const float4*)&sm[ybase + (ymt + 2 * kqi) * P2WS];
                s0 += p.x; s1 += p.y; s2 += p.z; s3 += p.w;
            }
            sm[S_Y2 + (4 * yq2g + 0) * 32 + yc] = fmaxf(s0 + bias2, 0.f);
            sm[S_Y2 + (4 * yq2g + 1) * 32 + yc] = fmaxf(s1 + bias2, 0.f);
            sm[S_Y2 + (4 * yq2g + 2) * 32 + yc] = fmaxf(s2 + bias2, 0.f);
            sm[S_Y2 + (4 * yq2g + 3) * 32 + yc] = fmaxf(s3 + bias2, 0.f);
        }
        __syncthreads();

        // layer3 partial: warp = 4-channel slice, lane = f
        {
            float acc = 0.f;
#pragma unroll
            for (int q2 = 0; q2 < 8; ++q2) {
                const float4 y2v = *(const float4*)&sm[S_Y2 + q2 * 32 + 4 * wrp];
                const float4 w3v = *(const float4*)&sm[S_W3S + ((q2 * 8 + wrp) * 32 + lane) * 4];
                acc = fmaf(w3v.x, y2v.x, acc);
                acc = fmaf(w3v.y, y2v.y, acc);
                acc = fmaf(w3v.z, y2v.z, acc);
                acc = fmaf(w3v.w, y2v.w, acc);
            }
            sm[S_P3 + wrp * 32 + lane] = acc;
        }
        // no barrier here: next iteration's top barrier (or tail below) covers P3
    }

    __syncthreads();
    if (wrp == 0) do_final(ebase + nel - 1);
}

extern "C" void kernel_launch(void* const* d_in, const int* in_sizes, int n_in,
                              void* d_out, int out_size) {
    const int*   gI  = (const int*)d_in[0];
    const int*   gJ  = (const int*)d_in[1];
    const int*   gK  = (const int*)d_in[2];
    const float* A   = (const float*)d_in[3];
    const float* B   = (const float*)d_in[4];
    const float* C   = (const float*)d_in[5];
    const float* W0  = (const float*)d_in[6];
    const float* b0  = (const float*)d_in[7];
    const float* W1  = (const float*)d_in[8];
    const float* b1  = (const float*)d_in[9];
    const float* W2  = (const float*)d_in[10];
    const float* b2  = (const float*)d_in[11];
    const float* W3  = (const float*)d_in[12];
    const float* b3  = (const float*)d_in[13];
    const float* FCW = (const float*)d_in[14];
    const float* FCB = (const float*)d_in[15];

    cudaFuncSetAttribute(ntc_fused, cudaFuncAttributeMaxDynamicSharedMemorySize, SMEM_BYTES);

    const int n = in_sizes[0];
    const int grid = (n + EPC - 1) / EPC;
    ntc_fused<<<grid, 256, SMEM_BYTES>>>(gI, gJ, gK, A, B, C, W0, b0, W1, b1, W2, b2,
                                         W3, b3, FCW, FCB, (float*)d_out, n);
}